// round 2
// baseline (speedup 1.0000x reference)
#include <cuda_runtime.h>
#include <math.h>
#include <stdint.h>

#define BB 8192
#define GG 256
#define EMBD 128
#define NHEAD 4
#define EVT 65536
#define TMAXN 196608  /* 8192 * 24 (counts in [8,24]) */

// ---------------- scratch (static device globals; no runtime allocation) ----
__device__ float g_w[BB * GG];          // w = c @ M1          (B,256)
__device__ float g_ck[BB * GG];         // ck = c @ Wk_n       (B,256)
__device__ float g_cadj[BB * GG];       // c * centre_gate     (B,256)
__device__ float g_M1[GG * GG];         // Wq_c @ Wk_c^T       (256,256)
__device__ float g_nadj[(size_t)TMAXN * GG];    // n * gate    (T,256)
__device__ float g_hn[(size_t)TMAXN * EMBD];    // n_adj @ W1  (T,128)
__device__ float g_hc[BB * EMBD];       // c_adj @ W1          (B,128)
__device__ float g_xc[BB * EMBD];       // GAT1 output at centers
__device__ float g_h2[BB * EMBD];       // xc @ W2
__device__ float g_s1n[(size_t)TMAXN * NHEAD];
__device__ float g_d1c[BB * NHEAD];
__device__ float g_fsn[TMAXN];
__device__ float g_fdn[TMAXN];
__device__ float g_fsc[BB];
__device__ float g_fdc[BB];
__device__ float g_s2[BB];
__device__ float g_d2[BB];
__device__ float g_e2v[EVT];
__device__ float g_vmax[BB];
__device__ float g_vsum[BB];

// ---------------- helpers ---------------------------------------------------
__device__ __forceinline__ float warpsum(float v) {
#pragma unroll
    for (int o = 16; o; o >>= 1) v += __shfl_xor_sync(0xffffffffu, v, o);
    return v;
}
__device__ __forceinline__ float warpmax(float v) {
#pragma unroll
    for (int o = 16; o; o >>= 1) v = fmaxf(v, __shfl_xor_sync(0xffffffffu, v, o));
    return v;
}
__device__ __forceinline__ void atomicMaxFloat(float* addr, float value) {
    if (value >= 0.f) atomicMax((int*)addr, __float_as_int(value));
    else              atomicMin((unsigned int*)addr, __float_as_uint(value));
}
__device__ __forceinline__ float lrelu02(float x) { return x > 0.f ? x : 0.2f * x; }
__device__ __forceinline__ float sigm(float x) { return 1.f / (1.f + expf(-x)); }

// ---------------- init ------------------------------------------------------
__global__ void init_kernel(float* __restrict__ out_xn) {
    int i = blockIdx.x * blockDim.x + threadIdx.x;
    if (i < BB * EMBD) out_xn[i] = 0.f;
    if (i < BB) { g_vmax[i] = -1e30f; g_vsum[i] = 0.f; }
}

// ---------------- M1 = Wq_c @ Wk_c^T  (256x256, K=128) -----------------------
__global__ void compute_M1(const float* __restrict__ Wq_c,
                           const float* __restrict__ Wk_c) {
    int p = blockIdx.x;                    // 0..255
    int tid = threadIdx.x, lane = tid & 31, warp = tid >> 5;
    __shared__ float sq[128];
    if (tid < 128) sq[tid] = Wq_c[p * 128 + tid];
    __syncthreads();
    for (int k = warp; k < 256; k += 8) {
        const float* row = Wk_c + (size_t)k * 128;
        float acc = 0.f;
#pragma unroll
        for (int i = 0; i < 4; i++) acc += row[lane + 32 * i] * sq[lane + 32 * i];
        acc = warpsum(acc);
        if (!lane) g_M1[p * 256 + k] = acc;
    }
}

// ---------------- generic fp32 GEMM: C(M,N) = A(M,K) @ B(K,N) ----------------
// 128x128 block tile, BK=8, 8x8 microtile, 256 threads.
__global__ void __launch_bounds__(256) sgemm128(
    const float* __restrict__ A, const float* __restrict__ Bm,
    float* __restrict__ C, int M, int N, int K) {
    __shared__ float As[8][128];
    __shared__ float Bs[8][128];
    int tid = threadIdx.x;
    int tx = tid & 15, ty = tid >> 4;
    int row0 = blockIdx.y * 128, col0 = blockIdx.x * 128;
    float acc[8][8] = {};
    int ar = tid >> 1;            // 0..127
    int ac = (tid & 1) * 4;       // 0 or 4
    int br = tid >> 5;            // 0..7
    int bc = (tid & 31) * 4;      // 0..124
    bool arow_ok = (row0 + ar) < M;
    const float* Aptr = A + (size_t)(row0 + ar) * K + ac;
    for (int k0 = 0; k0 < K; k0 += 8) {
        float4 av = arow_ok ? *(const float4*)(Aptr + k0) : make_float4(0, 0, 0, 0);
        As[ac + 0][ar] = av.x; As[ac + 1][ar] = av.y;
        As[ac + 2][ar] = av.z; As[ac + 3][ar] = av.w;
        float4 bv = *(const float4*)(Bm + (size_t)(k0 + br) * N + col0 + bc);
        *(float4*)&Bs[br][bc] = bv;
        __syncthreads();
#pragma unroll
        for (int kk = 0; kk < 8; kk++) {
            float a[8], b[8];
#pragma unroll
            for (int i = 0; i < 8; i++) a[i] = As[kk][ty * 8 + i];
#pragma unroll
            for (int j = 0; j < 8; j++) b[j] = Bs[kk][tx * 8 + j];
#pragma unroll
            for (int i = 0; i < 8; i++)
#pragma unroll
                for (int j = 0; j < 8; j++) acc[i][j] += a[i] * b[j];
        }
        __syncthreads();
    }
#pragma unroll
    for (int i = 0; i < 8; i++) {
        int r = row0 + ty * 8 + i;
        if (r >= M) break;
#pragma unroll
        for (int j = 0; j < 8; j += 4)
            *(float4*)(C + (size_t)r * N + col0 + tx * 8 + j) =
                make_float4(acc[i][j], acc[i][j + 1], acc[i][j + 2], acc[i][j + 3]);
    }
}

// ---------------- gate GEMM: nq = n @ Wq_n, fused epilogue -------------------
// n_adj = n * tanh(nq * ck[seg]);   attn_all[g] = gate row at t == offs[g]
__global__ void __launch_bounds__(256) sgemm128_gate(
    const float* __restrict__ A /*n*/, const float* __restrict__ Bm /*Wq_n*/,
    float* __restrict__ Cout /*n_adj*/, const float* __restrict__ ck,
    const int* __restrict__ seg, const int* __restrict__ offs,
    float* __restrict__ out_attn, int M /*T*/) {
    const int N = 256, K = 256;
    __shared__ float As[8][128];
    __shared__ float Bs[8][128];
    int tid = threadIdx.x;
    int tx = tid & 15, ty = tid >> 4;
    int row0 = blockIdx.y * 128, col0 = blockIdx.x * 128;
    float acc[8][8] = {};
    int ar = tid >> 1;
    int ac = (tid & 1) * 4;
    int br = tid >> 5;
    int bc = (tid & 31) * 4;
    bool arow_ok = (row0 + ar) < M;
    const float* Aptr = A + (size_t)(row0 + ar) * K + ac;
    for (int k0 = 0; k0 < K; k0 += 8) {
        float4 av = arow_ok ? *(const float4*)(Aptr + k0) : make_float4(0, 0, 0, 0);
        As[ac + 0][ar] = av.x; As[ac + 1][ar] = av.y;
        As[ac + 2][ar] = av.z; As[ac + 3][ar] = av.w;
        float4 bv = *(const float4*)(Bm + (size_t)(k0 + br) * N + col0 + bc);
        *(float4*)&Bs[br][bc] = bv;
        __syncthreads();
#pragma unroll
        for (int kk = 0; kk < 8; kk++) {
            float a[8], b[8];
#pragma unroll
            for (int i = 0; i < 8; i++) a[i] = As[kk][ty * 8 + i];
#pragma unroll
            for (int j = 0; j < 8; j++) b[j] = Bs[kk][tx * 8 + j];
#pragma unroll
            for (int i = 0; i < 8; i++)
#pragma unroll
                for (int j = 0; j < 8; j++) acc[i][j] += a[i] * b[j];
        }
        __syncthreads();
    }
#pragma unroll
    for (int i = 0; i < 8; i++) {
        int r = row0 + ty * 8 + i;
        if (r >= M) break;
        int sg = seg[r];
        bool first = (offs[sg] == r);
        const float* ckrow = ck + (size_t)sg * 256;
#pragma unroll
        for (int j = 0; j < 8; j++) {
            int c = col0 + tx * 8 + j;
            float gate = tanhf(acc[i][j] * ckrow[c]);
            float nv = A[(size_t)r * 256 + c];
            Cout[(size_t)r * 256 + c] = nv * gate;
            if (first) out_attn[(size_t)sg * 256 + c] = gate;
        }
    }
}

// ---------------- stage A: per-group cross-attention (center) ----------------
__global__ void __launch_bounds__(128) stageA(
    const float* __restrict__ cin, const float* __restrict__ nin,
    const float* __restrict__ counts_f, const int* __restrict__ offs,
    float* __restrict__ out_gate, float* __restrict__ out_nein) {
    int g = blockIdx.x;
    int tid = threadIdx.x, lane = tid & 31, warp = tid >> 5;
    int base = offs[g];
    int cnt = (int)(counts_f[g] + 0.5f);
    __shared__ float s_w[256];
    __shared__ float s_attn[32];
    s_w[tid] = g_w[(size_t)g * 256 + tid];
    s_w[tid + 128] = g_w[(size_t)g * 256 + 128 + tid];
    __syncthreads();
    for (int t = warp; t < cnt; t += 4) {
        const float* row = nin + (size_t)(base + t) * 256;
        float acc = 0.f;
#pragma unroll
        for (int i = 0; i < 8; i++) acc += row[lane + 32 * i] * s_w[lane + 32 * i];
        acc = warpsum(acc);
        if (!lane) s_attn[t] = acc * 0.08838834764831845f;  // 1/sqrt(128)
    }
    __syncthreads();
    if (tid == 0) {
        float m = -1e30f;
        for (int t = 0; t < cnt; t++) m = fmaxf(m, s_attn[t]);
        float s = 0.f;
        for (int t = 0; t < cnt; t++) { float e = expf(s_attn[t] - m); s_attn[t] = e; s += e; }
        float inv = 1.f / (s + 1e-16f);
        for (int t = 0; t < cnt; t++) s_attn[t] *= inv;
    }
    __syncthreads();
    float acc0 = 0.f, acc1 = 0.f, sum0 = 0.f, sum1 = 0.f;
    for (int t = 0; t < cnt; t++) {
        const float* row = nin + (size_t)(base + t) * 256;
        float v0 = row[tid], v1 = row[tid + 128];
        float a = s_attn[t];
        acc0 += a * v0; acc1 += a * v1;
        sum0 += v0;     sum1 += v1;
    }
    float gate0 = tanhf(acc0), gate1 = tanhf(acc1);
    size_t o = (size_t)g * 256 + tid;
    float c0 = cin[o], c1 = cin[o + 128];
    out_gate[o] = gate0;            out_gate[o + 128] = gate1;
    g_cadj[o] = c0 * gate0;         g_cadj[o + 128] = c1 * gate1;
    out_nein[o] = c0 + sum0;        out_nein[o + 128] = c1 + sum1;
}

// ---------------- neighb_expr = segsum(n_adj)/counts -------------------------
__global__ void __launch_bounds__(128) segmean_nadj(
    const float* __restrict__ counts_f, const int* __restrict__ offs,
    float* __restrict__ out_ne) {
    int g = blockIdx.x;
    int tid = threadIdx.x;
    int base = offs[g];
    int cnt = (int)(counts_f[g] + 0.5f);
    float inv = 1.f / counts_f[g];
    float s0 = 0.f, s1 = 0.f;
    for (int t = 0; t < cnt; t++) {
        const float* row = g_nadj + (size_t)(base + t) * 256;
        s0 += row[tid]; s1 += row[tid + 128];
    }
    out_ne[(size_t)g * 256 + tid] = s0 * inv;
    out_ne[(size_t)g * 256 + 128 + tid] = s1 * inv;
}

// ---------------- per-node scalars (neighbors): s1, fs, fd -------------------
__global__ void node_scalars_n(const float* __restrict__ a_src1,
                               const float* __restrict__ a_feat, int T) {
    int row = blockIdx.x * 4 + (threadIdx.x >> 5);
    if (row >= T) return;
    int lane = threadIdx.x & 31;
    const float* h = g_hn + (size_t)row * 128;
    float v[4];
#pragma unroll
    for (int i = 0; i < 4; i++) v[i] = h[lane + 32 * i];
#pragma unroll
    for (int i = 0; i < 4; i++) {
        float s = warpsum(v[i] * a_src1[i * 32 + lane]);
        if (!lane) g_s1n[(size_t)row * 4 + i] = s;
    }
    float fs = 0.f, fd = 0.f;
#pragma unroll
    for (int i = 0; i < 4; i++) {
        fs += v[i] * a_feat[i * 32 + lane];
        fd += v[i] * a_feat[128 + i * 32 + lane];
    }
    fs = warpsum(fs); fd = warpsum(fd);
    if (!lane) { g_fsn[row] = fs; g_fdn[row] = fd; }
}

// ---------------- per-node scalars (centers): d1, fs, fd ---------------------
__global__ void node_scalars_c(const float* __restrict__ a_dst1,
                               const float* __restrict__ a_feat) {
    int row = blockIdx.x * 4 + (threadIdx.x >> 5);
    if (row >= BB) return;
    int lane = threadIdx.x & 31;
    const float* h = g_hc + (size_t)row * 128;
    float v[4];
#pragma unroll
    for (int i = 0; i < 4; i++) v[i] = h[lane + 32 * i];
#pragma unroll
    for (int i = 0; i < 4; i++) {
        float d = warpsum(v[i] * a_dst1[i * 32 + lane]);
        if (!lane) g_d1c[row * 4 + i] = d;
    }
    float fs = 0.f, fd = 0.f;
#pragma unroll
    for (int i = 0; i < 4; i++) {
        fs += v[i] * a_feat[i * 32 + lane];
        fd += v[i] * a_feat[128 + i * 32 + lane];
    }
    fs = warpsum(fs); fd = warpsum(fd);
    if (!lane) { g_fsc[row] = fs; g_fdc[row] = fd; }
}

// ---------------- GAT1: per-group softmax + aggregation + edges_weights ------
__global__ void __launch_bounds__(128) gat1(
    const float* __restrict__ counts_f, const int* __restrict__ offs,
    const int* __restrict__ edges, int T, float* __restrict__ out_ew) {
    int g = blockIdx.x;
    int tid = threadIdx.x, lane = tid & 31, warp = tid >> 5;
    int base = offs[g];
    int cnt = (int)(counts_f[g] + 0.5f);
    int E2 = 2 * T;
    __shared__ float s_alpha[32][4];
    int head = warp;
    float d1 = g_d1c[g * 4 + head];
    float m = -1e30f;
    for (int t = lane; t < cnt; t += 32) {
        float e = lrelu02(g_s1n[(size_t)(base + t) * 4 + head] + d1);
        s_alpha[t][head] = e;
        m = fmaxf(m, e);
    }
    m = warpmax(m);
    float ssum = 0.f;
    for (int t = lane; t < cnt; t += 32) {
        float ex = expf(s_alpha[t][head] - m);
        s_alpha[t][head] = ex;
        ssum += ex;
    }
    ssum = warpsum(ssum);
    float inv = 1.f / (ssum + 1e-16f);
    for (int t = lane; t < cnt; t += 32) s_alpha[t][head] *= inv;
    __syncthreads();
    // x at center g (128 floats)
    int h4 = tid >> 5;
    float acc = 0.f;
    for (int t = 0; t < cnt; t++)
        acc += s_alpha[t][h4] * g_hn[(size_t)(base + t) * 128 + tid];
    g_xc[(size_t)g * 128 + tid] = acc;
    // edges_weights
    if (tid < cnt) {
        int t = tid;
        int ei = base + t;             // first-half edge index
        float am = 0.25f * (s_alpha[t][0] + s_alpha[t][1] + s_alpha[t][2] + s_alpha[t][3]);
        float a2 = sigm(g_fsn[ei] + g_fdc[g]);
        float4 r1 = make_float4((float)edges[ei], (float)edges[E2 + ei], am, a2);
        *(float4*)(out_ew + (size_t)ei * 4) = r1;
        int ej = T + ei;               // second-half edge index
        float a2b = sigm(g_fsc[g] + g_fdn[ei]);
        float4 r2 = make_float4((float)edges[ej], (float)edges[E2 + ej], 1.0f, a2b);
        *(float4*)(out_ew + (size_t)ej * 4) = r2;
    }
}

// ---------------- h2 scalars: s2 = h2·a_src2, d2 = h2·a_dst2 -----------------
__global__ void h2_scalars(const float* __restrict__ a_src2,
                           const float* __restrict__ a_dst2) {
    int row = blockIdx.x * 4 + (threadIdx.x >> 5);
    if (row >= BB) return;
    int lane = threadIdx.x & 31;
    const float* h = g_h2 + (size_t)row * 128;
    float s = 0.f, d = 0.f;
#pragma unroll
    for (int i = 0; i < 4; i++) {
        float v = h[lane + 32 * i];
        s += v * a_src2[lane + 32 * i];
        d += v * a_dst2[lane + 32 * i];
    }
    s = warpsum(s); d = warpsum(d);
    if (!lane) { g_s2[row] = s; g_d2[row] = d; }
}

// ---------------- VT graph softmax (random topology, atomics) ----------------
__global__ void vt_pass1(const int* __restrict__ evt) {
    int i = blockIdx.x * blockDim.x + threadIdx.x;
    if (i >= EVT) return;
    int sv = evt[i], dv = evt[EVT + i];
    float e = lrelu02(g_s2[sv] + g_d2[dv]);
    g_e2v[i] = e;
    atomicMaxFloat(&g_vmax[dv], e);
}
__global__ void vt_pass2(const int* __restrict__ evt) {
    int i = blockIdx.x * blockDim.x + threadIdx.x;
    if (i >= EVT) return;
    int dv = evt[EVT + i];
    float ex = expf(g_e2v[i] - g_vmax[dv]);
    g_e2v[i] = ex;
    atomicAdd(&g_vsum[dv], ex);
}
__global__ void __launch_bounds__(128) vt_pass3(const int* __restrict__ evt,
                                                float* __restrict__ out_alpha,
                                                float* __restrict__ out_xn) {
    int i = blockIdx.x;
    int sv = evt[i], dv = evt[EVT + i];
    float alpha = g_e2v[i] / (g_vsum[dv] + 1e-16f);
    if (threadIdx.x == 0) out_alpha[i] = alpha;
    atomicAdd(&out_xn[(size_t)dv * 128 + threadIdx.x],
              alpha * g_h2[(size_t)sv * 128 + threadIdx.x]);
}

// ---------------- host launcher ----------------------------------------------
extern "C" void kernel_launch(void* const* d_in, const int* in_sizes, int n_in,
                              void* d_out, int out_size) {
    const float* c_in    = (const float*)d_in[0];
    const float* nb_in   = (const float*)d_in[1];
    const float* counts  = (const float*)d_in[2];
    const float* Wq_c    = (const float*)d_in[3];
    const float* Wk_c    = (const float*)d_in[4];
    const float* Wq_n    = (const float*)d_in[5];
    const float* Wk_n    = (const float*)d_in[6];
    const float* W1      = (const float*)d_in[7];
    const float* a_src1  = (const float*)d_in[8];
    const float* a_dst1  = (const float*)d_in[9];
    const float* a_feat  = (const float*)d_in[10];
    const float* W2      = (const float*)d_in[11];
    const float* a_src2  = (const float*)d_in[12];
    const float* a_dst2  = (const float*)d_in[13];
    const int*   seg     = (const int*)d_in[14];
    // d_in[15] centre_pos, d_in[16] neighb_pos: implied by contiguous layout
    const int*   offs    = (const int*)d_in[17];
    const int*   edges   = (const int*)d_in[18];
    const int*   evt     = (const int*)d_in[19];
    int T = in_sizes[1] / GG;

    float* out = (float*)d_out;
    float* out_xn   = out;                              // (B,128)
    float* out_gate = out_xn + (size_t)BB * EMBD;       // (B,256)
    float* out_attn = out_gate + (size_t)BB * GG;       // (B,256)
    float* out_ne   = out_attn + (size_t)BB * GG;       // (B,256)
    float* out_nein = out_ne + (size_t)BB * GG;         // (B,256)
    float* out_ew   = out_nein + (size_t)BB * GG;       // (2T,4)
    float* out_avt  = out_ew + (size_t)8 * T;           // (Evt,)

    float *p_w, *p_ck, *p_M1, *p_cadj, *p_nadj, *p_hn, *p_hc, *p_xc, *p_h2;
    cudaGetSymbolAddress((void**)&p_w, g_w);
    cudaGetSymbolAddress((void**)&p_ck, g_ck);
    cudaGetSymbolAddress((void**)&p_M1, g_M1);
    cudaGetSymbolAddress((void**)&p_cadj, g_cadj);
    cudaGetSymbolAddress((void**)&p_nadj, g_nadj);
    cudaGetSymbolAddress((void**)&p_hn, g_hn);
    cudaGetSymbolAddress((void**)&p_hc, g_hc);
    cudaGetSymbolAddress((void**)&p_xc, g_xc);
    cudaGetSymbolAddress((void**)&p_h2, g_h2);

    init_kernel<<<(BB * EMBD + 255) / 256, 256>>>(out_xn);
    compute_M1<<<GG, 256>>>(Wq_c, Wk_c);

    // w = c @ M1, ck = c @ Wk_n     (8192 x 256 x 256 each)
    sgemm128<<<dim3(2, BB / 128), 256>>>(c_in, p_M1, p_w, BB, 256, 256);
    sgemm128<<<dim3(2, BB / 128), 256>>>(c_in, Wk_n, p_ck, BB, 256, 256);

    stageA<<<BB, 128>>>(c_in, nb_in, counts, offs, out_gate, out_nein);

    // n_adj = n * tanh((n@Wq_n) * ck[seg]) + attn_all     (T x 256 x 256)
    sgemm128_gate<<<dim3(2, (T + 127) / 128), 256>>>(nb_in, Wq_n, p_nadj, p_ck,
                                                     seg, offs, out_attn, T);
    segmean_nadj<<<BB, 128>>>(counts, offs, out_ne);

    // h = node_attr @ W1, split neighbor/center
    sgemm128<<<dim3(1, (T + 127) / 128), 256>>>(p_nadj, W1, p_hn, T, 128, 256);
    sgemm128<<<dim3(1, BB / 128), 256>>>(p_cadj, W1, p_hc, BB, 128, 256);

    node_scalars_n<<<(T + 3) / 4, 128>>>(a_src1, a_feat, T);
    node_scalars_c<<<BB / 4, 128>>>(a_dst1, a_feat);

    gat1<<<BB, 128>>>(counts, offs, edges, T, out_ew);

    // h2 = xc @ W2     (8192 x 128 x 128)
    sgemm128<<<dim3(1, BB / 128), 256>>>(p_xc, W2, p_h2, BB, 128, 128);
    h2_scalars<<<BB / 4, 128>>>(a_src2, a_dst2);

    vt_pass1<<<(EVT + 255) / 256, 256>>>(evt);
    vt_pass2<<<(EVT + 255) / 256, 256>>>(evt);
    vt_pass3<<<EVT, 128>>>(evt, out_avt, out_xn);
}

// round 3
// speedup vs baseline: 1.1911x; 1.1911x over previous
#include <cuda_runtime.h>
#include <math.h>
#include <stdint.h>

#define BB 8192
#define GG 256
#define EMBD 128
#define NHEAD 4
#define EVT 65536
#define TMAXN 196608  /* 8192 * 24 (counts in [8,24]) */

// ---------------- scratch (static device globals; no runtime allocation) ----
__device__ float g_w[BB * GG];          // w = c @ M1          (B,256)
__device__ float g_ck[BB * GG];         // ck = c @ Wk_n       (B,256)
__device__ float g_cadj[BB * GG];       // c * centre_gate     (B,256)
__device__ float g_M1[GG * GG];         // Wq_c @ Wk_c^T       (256,256)
__device__ float g_nadj[(size_t)TMAXN * GG];    // n * gate    (T,256)
__device__ float g_hn[(size_t)TMAXN * EMBD];    // n_adj @ W1  (T,128)
__device__ float g_hc[BB * EMBD];       // c_adj @ W1          (B,128)
__device__ float g_xc[BB * EMBD];       // GAT1 output at centers
__device__ float g_h2[BB * EMBD];       // xc @ W2
__device__ float g_s1n[(size_t)TMAXN * NHEAD];
__device__ float g_d1c[BB * NHEAD];
__device__ float g_fsn[TMAXN];
__device__ float g_fdn[TMAXN];
__device__ float g_fsc[BB];
__device__ float g_fdc[BB];
__device__ float g_s2[BB];
__device__ float g_d2[BB];
__device__ float g_e2v[EVT];
__device__ float g_vmax[BB];
__device__ float g_vsum[BB];

// ---------------- helpers ---------------------------------------------------
__device__ __forceinline__ float warpsum(float v) {
#pragma unroll
    for (int o = 16; o; o >>= 1) v += __shfl_xor_sync(0xffffffffu, v, o);
    return v;
}
__device__ __forceinline__ float warpmax(float v) {
#pragma unroll
    for (int o = 16; o; o >>= 1) v = fmaxf(v, __shfl_xor_sync(0xffffffffu, v, o));
    return v;
}
__device__ __forceinline__ void atomicMaxFloat(float* addr, float value) {
    if (value >= 0.f) atomicMax((int*)addr, __float_as_int(value));
    else              atomicMin((unsigned int*)addr, __float_as_uint(value));
}
__device__ __forceinline__ float lrelu02(float x) { return x > 0.f ? x : 0.2f * x; }
__device__ __forceinline__ float sigm(float x) { return 1.f / (1.f + expf(-x)); }

// ---------------- init ------------------------------------------------------
__global__ void init_kernel(float* __restrict__ out_xn) {
    int i = blockIdx.x * blockDim.x + threadIdx.x;
    if (i < BB * EMBD) out_xn[i] = 0.f;
    if (i < BB) { g_vmax[i] = -1e30f; g_vsum[i] = 0.f; }
}

// ---------------- M1 = Wq_c @ Wk_c^T  (256x256, K=128) -----------------------
__global__ void compute_M1(const float* __restrict__ Wq_c,
                           const float* __restrict__ Wk_c) {
    int p = blockIdx.x;                    // 0..255
    int tid = threadIdx.x, lane = tid & 31, warp = tid >> 5;
    __shared__ float sq[128];
    if (tid < 128) sq[tid] = Wq_c[p * 128 + tid];
    __syncthreads();
    for (int k = warp; k < 256; k += 8) {
        const float* row = Wk_c + (size_t)k * 128;
        float acc = 0.f;
#pragma unroll
        for (int i = 0; i < 4; i++) acc += row[lane + 32 * i] * sq[lane + 32 * i];
        acc = warpsum(acc);
        if (!lane) g_M1[p * 256 + k] = acc;
    }
}

// =============================================================================
// Double-buffered SGEMM core: 128x128 tile, BK=16, 8x8 microtile, 256 thr.
// Smem: As[2][16][132] (padded, transposed), Bs[2][16][128].
// One __syncthreads per 16 K-steps; global loads prefetched into registers.
// =============================================================================
#define GEMM_MAINLOOP(A_, B_, M_, N_, K_, row0_, col0_)                        \
    float acc[8][8] = {};                                                      \
    {                                                                          \
        const int tid = threadIdx.x;                                          \
        const int tx = tid & 15, ty = tid >> 4;                               \
        /* A load mapping: 2 float4 per thread */                              \
        const int ar0 = tid >> 2;            /* 0..63  (l=0) */                \
        const int ar1 = ar0 + 64;            /* 64..127 (l=1) */               \
        const int ac  = (tid & 3) * 4;       /* 0,4,8,12 */                    \
        const int br0 = tid >> 5;            /* 0..7 */                        \
        const int br1 = br0 + 8;             /* 8..15 */                       \
        const int bc  = (tid & 31) * 4;                                        \
        const bool ok0 = (row0_ + ar0) < (M_);                                 \
        const bool ok1 = (row0_ + ar1) < (M_);                                 \
        const float* Ap0 = (A_) + (size_t)(row0_ + ar0) * (K_) + ac;          \
        const float* Ap1 = (A_) + (size_t)(row0_ + ar1) * (K_) + ac;          \
        const float* Bp0 = (B_) + (size_t)br0 * (N_) + col0_ + bc;            \
        const float* Bp1 = (B_) + (size_t)br1 * (N_) + col0_ + bc;            \
        float4 ga0 = ok0 ? *(const float4*)(Ap0) : make_float4(0,0,0,0);      \
        float4 ga1 = ok1 ? *(const float4*)(Ap1) : make_float4(0,0,0,0);      \
        float4 gb0 = *(const float4*)(Bp0);                                   \
        float4 gb1 = *(const float4*)(Bp1);                                   \
        int buf = 0;                                                           \
        As[0][ac+0][ar0]=ga0.x; As[0][ac+1][ar0]=ga0.y;                        \
        As[0][ac+2][ar0]=ga0.z; As[0][ac+3][ar0]=ga0.w;                        \
        As[0][ac+0][ar1]=ga1.x; As[0][ac+1][ar1]=ga1.y;                        \
        As[0][ac+2][ar1]=ga1.z; As[0][ac+3][ar1]=ga1.w;                        \
        *(float4*)&Bs[0][br0][bc] = gb0;                                       \
        *(float4*)&Bs[0][br1][bc] = gb1;                                       \
        __syncthreads();                                                       \
        for (int k0 = 16; k0 < (K_); k0 += 16) {                               \
            ga0 = ok0 ? *(const float4*)(Ap0 + k0) : make_float4(0,0,0,0);    \
            ga1 = ok1 ? *(const float4*)(Ap1 + k0) : make_float4(0,0,0,0);    \
            gb0 = *(const float4*)(Bp0 + (size_t)k0 * (N_));                  \
            gb1 = *(const float4*)(Bp1 + (size_t)k0 * (N_));                  \
            _Pragma("unroll")                                                  \
            for (int kk = 0; kk < 16; kk++) {                                  \
                float a[8], b[8];                                              \
                _Pragma("unroll")                                              \
                for (int i = 0; i < 8; i++) a[i] = As[buf][kk][ty*8+i];        \
                _Pragma("unroll")                                              \
                for (int j = 0; j < 8; j++) b[j] = Bs[buf][kk][tx*8+j];        \
                _Pragma("unroll")                                              \
                for (int i = 0; i < 8; i++)                                    \
                    _Pragma("unroll")                                          \
                    for (int j = 0; j < 8; j++) acc[i][j] += a[i]*b[j];        \
            }                                                                  \
            int nb = buf ^ 1;                                                  \
            As[nb][ac+0][ar0]=ga0.x; As[nb][ac+1][ar0]=ga0.y;                  \
            As[nb][ac+2][ar0]=ga0.z; As[nb][ac+3][ar0]=ga0.w;                  \
            As[nb][ac+0][ar1]=ga1.x; As[nb][ac+1][ar1]=ga1.y;                  \
            As[nb][ac+2][ar1]=ga1.z; As[nb][ac+3][ar1]=ga1.w;                  \
            *(float4*)&Bs[nb][br0][bc] = gb0;                                  \
            *(float4*)&Bs[nb][br1][bc] = gb1;                                  \
            __syncthreads();                                                   \
            buf = nb;                                                          \
        }                                                                      \
        _Pragma("unroll")                                                      \
        for (int kk = 0; kk < 16; kk++) {                                      \
            float a[8], b[8];                                                  \
            _Pragma("unroll")                                                  \
            for (int i = 0; i < 8; i++) a[i] = As[buf][kk][ty*8+i];            \
            _Pragma("unroll")                                                  \
            for (int j = 0; j < 8; j++) b[j] = Bs[buf][kk][tx*8+j];            \
            _Pragma("unroll")                                                  \
            for (int i = 0; i < 8; i++)                                        \
                _Pragma("unroll")                                              \
                for (int j = 0; j < 8; j++) acc[i][j] += a[i]*b[j];            \
        }                                                                      \
    }

// ---------------- generic GEMM ----------------------------------------------
__global__ void __launch_bounds__(256, 2) sgemm_db(
    const float* __restrict__ A, const float* __restrict__ Bm,
    float* __restrict__ C, int M, int N, int K) {
    __shared__ float As[2][16][132];
    __shared__ float Bs[2][16][128];
    int row0 = blockIdx.y * 128, col0 = blockIdx.x * 128;
    GEMM_MAINLOOP(A, Bm, M, N, K, row0, col0);
    int tx = threadIdx.x & 15, ty = threadIdx.x >> 4;
#pragma unroll
    for (int i = 0; i < 8; i++) {
        int r = row0 + ty * 8 + i;
        if (r >= M) break;
#pragma unroll
        for (int j = 0; j < 8; j += 4)
            *(float4*)(C + (size_t)r * N + col0 + tx * 8 + j) =
                make_float4(acc[i][j], acc[i][j+1], acc[i][j+2], acc[i][j+3]);
    }
}

// ---------------- dual-B GEMM: same A, two (B,C) pairs, select by z ----------
__global__ void __launch_bounds__(256, 2) sgemm_db_dualB(
    const float* __restrict__ A,
    const float* __restrict__ B0, const float* __restrict__ B1,
    float* __restrict__ C0, float* __restrict__ C1, int M, int N, int K) {
    __shared__ float As[2][16][132];
    __shared__ float Bs[2][16][128];
    const float* Bm = blockIdx.z ? B1 : B0;
    float* C = blockIdx.z ? C1 : C0;
    int row0 = blockIdx.y * 128, col0 = blockIdx.x * 128;
    GEMM_MAINLOOP(A, Bm, M, N, K, row0, col0);
    int tx = threadIdx.x & 15, ty = threadIdx.x >> 4;
#pragma unroll
    for (int i = 0; i < 8; i++) {
        int r = row0 + ty * 8 + i;
        if (r >= M) break;
#pragma unroll
        for (int j = 0; j < 8; j += 4)
            *(float4*)(C + (size_t)r * N + col0 + tx * 8 + j) =
                make_float4(acc[i][j], acc[i][j+1], acc[i][j+2], acc[i][j+3]);
    }
}

// ---------------- dual-A GEMM: same B, two (A,C) pairs (hn then hc) ----------
__global__ void __launch_bounds__(256, 2) sgemm_db_dualA(
    const float* __restrict__ A0, const float* __restrict__ A1,
    const float* __restrict__ Bm,
    float* __restrict__ C0, float* __restrict__ C1,
    int M0, int M1, int tiles0, int N, int K) {
    __shared__ float As[2][16][132];
    __shared__ float Bs[2][16][128];
    int t = blockIdx.y;
    const float* A; float* C; int M; int row0;
    if (t < tiles0) { A = A0; C = C0; M = M0; row0 = t * 128; }
    else            { A = A1; C = C1; M = M1; row0 = (t - tiles0) * 128; }
    int col0 = blockIdx.x * 128;
    GEMM_MAINLOOP(A, Bm, M, N, K, row0, col0);
    int tx = threadIdx.x & 15, ty = threadIdx.x >> 4;
#pragma unroll
    for (int i = 0; i < 8; i++) {
        int r = row0 + ty * 8 + i;
        if (r >= M) break;
#pragma unroll
        for (int j = 0; j < 8; j += 4)
            *(float4*)(C + (size_t)r * N + col0 + tx * 8 + j) =
                make_float4(acc[i][j], acc[i][j+1], acc[i][j+2], acc[i][j+3]);
    }
}

// ---------------- gate GEMM: nq = n @ Wq_n, fused tanh-gate epilogue ---------
__global__ void __launch_bounds__(256, 2) sgemm_db_gate(
    const float* __restrict__ A /*n*/, const float* __restrict__ Bm /*Wq_n*/,
    float* __restrict__ Cout /*n_adj*/, const float* __restrict__ ck,
    const int* __restrict__ seg, const int* __restrict__ offs,
    float* __restrict__ out_attn, int M /*T*/) {
    const int N = 256, K = 256;
    __shared__ float As[2][16][132];
    __shared__ float Bs[2][16][128];
    int row0 = blockIdx.y * 128, col0 = blockIdx.x * 128;
    GEMM_MAINLOOP(A, Bm, M, N, K, row0, col0);
    int tx = threadIdx.x & 15, ty = threadIdx.x >> 4;
#pragma unroll
    for (int i = 0; i < 8; i++) {
        int r = row0 + ty * 8 + i;
        if (r >= M) break;
        int sg = seg[r];
        bool first = (offs[sg] == r);
        const float* ckrow = ck + (size_t)sg * 256;
#pragma unroll
        for (int j = 0; j < 8; j++) {
            int c = col0 + tx * 8 + j;
            float gate = tanhf(acc[i][j] * ckrow[c]);
            float nv = A[(size_t)r * 256 + c];
            Cout[(size_t)r * 256 + c] = nv * gate;
            if (first) out_attn[(size_t)sg * 256 + c] = gate;
        }
    }
}

// ---------------- stage A: per-group cross-attention (center) ----------------
__global__ void __launch_bounds__(128) stageA(
    const float* __restrict__ cin, const float* __restrict__ nin,
    const float* __restrict__ counts_f, const int* __restrict__ offs,
    float* __restrict__ out_gate, float* __restrict__ out_nein) {
    int g = blockIdx.x;
    int tid = threadIdx.x, lane = tid & 31, warp = tid >> 5;
    int base = offs[g];
    int cnt = (int)(counts_f[g] + 0.5f);
    __shared__ float s_w[256];
    __shared__ float s_attn[32];
    s_w[tid] = g_w[(size_t)g * 256 + tid];
    s_w[tid + 128] = g_w[(size_t)g * 256 + 128 + tid];
    __syncthreads();
    for (int t = warp; t < cnt; t += 4) {
        const float* row = nin + (size_t)(base + t) * 256;
        float acc = 0.f;
#pragma unroll
        for (int i = 0; i < 8; i++) acc += row[lane + 32 * i] * s_w[lane + 32 * i];
        acc = warpsum(acc);
        if (!lane) s_attn[t] = acc * 0.08838834764831845f;  // 1/sqrt(128)
    }
    __syncthreads();
    if (tid == 0) {
        float m = -1e30f;
        for (int t = 0; t < cnt; t++) m = fmaxf(m, s_attn[t]);
        float s = 0.f;
        for (int t = 0; t < cnt; t++) { float e = expf(s_attn[t] - m); s_attn[t] = e; s += e; }
        float inv = 1.f / (s + 1e-16f);
        for (int t = 0; t < cnt; t++) s_attn[t] *= inv;
    }
    __syncthreads();
    float acc0 = 0.f, acc1 = 0.f, sum0 = 0.f, sum1 = 0.f;
    for (int t = 0; t < cnt; t++) {
        const float* row = nin + (size_t)(base + t) * 256;
        float v0 = row[tid], v1 = row[tid + 128];
        float a = s_attn[t];
        acc0 += a * v0; acc1 += a * v1;
        sum0 += v0;     sum1 += v1;
    }
    float gate0 = tanhf(acc0), gate1 = tanhf(acc1);
    size_t o = (size_t)g * 256 + tid;
    float c0 = cin[o], c1 = cin[o + 128];
    out_gate[o] = gate0;            out_gate[o + 128] = gate1;
    g_cadj[o] = c0 * gate0;         g_cadj[o + 128] = c1 * gate1;
    out_nein[o] = c0 + sum0;        out_nein[o + 128] = c1 + sum1;
}

// ---------------- neighb_expr = segsum(n_adj)/counts -------------------------
__global__ void __launch_bounds__(128) segmean_nadj(
    const float* __restrict__ counts_f, const int* __restrict__ offs,
    float* __restrict__ out_ne) {
    int g = blockIdx.x;
    int tid = threadIdx.x;
    int base = offs[g];
    int cnt = (int)(counts_f[g] + 0.5f);
    float inv = 1.f / counts_f[g];
    float s0 = 0.f, s1 = 0.f;
    for (int t = 0; t < cnt; t++) {
        const float* row = g_nadj + (size_t)(base + t) * 256;
        s0 += row[tid]; s1 += row[tid + 128];
    }
    out_ne[(size_t)g * 256 + tid] = s0 * inv;
    out_ne[(size_t)g * 256 + 128 + tid] = s1 * inv;
}

// ---------------- per-node scalars (neighbors): s1, fs, fd -------------------
__global__ void node_scalars_n(const float* __restrict__ a_src1,
                               const float* __restrict__ a_feat, int T) {
    int row = blockIdx.x * 4 + (threadIdx.x >> 5);
    if (row >= T) return;
    int lane = threadIdx.x & 31;
    const float* h = g_hn + (size_t)row * 128;
    float v[4];
#pragma unroll
    for (int i = 0; i < 4; i++) v[i] = h[lane + 32 * i];
#pragma unroll
    for (int i = 0; i < 4; i++) {
        float s = warpsum(v[i] * a_src1[i * 32 + lane]);
        if (!lane) g_s1n[(size_t)row * 4 + i] = s;
    }
    float fs = 0.f, fd = 0.f;
#pragma unroll
    for (int i = 0; i < 4; i++) {
        fs += v[i] * a_feat[i * 32 + lane];
        fd += v[i] * a_feat[128 + i * 32 + lane];
    }
    fs = warpsum(fs); fd = warpsum(fd);
    if (!lane) { g_fsn[row] = fs; g_fdn[row] = fd; }
}

// ---------------- per-node scalars (centers): d1, fs, fd ---------------------
__global__ void node_scalars_c(const float* __restrict__ a_dst1,
                               const float* __restrict__ a_feat) {
    int row = blockIdx.x * 4 + (threadIdx.x >> 5);
    if (row >= BB) return;
    int lane = threadIdx.x & 31;
    const float* h = g_hc + (size_t)row * 128;
    float v[4];
#pragma unroll
    for (int i = 0; i < 4; i++) v[i] = h[lane + 32 * i];
#pragma unroll
    for (int i = 0; i < 4; i++) {
        float d = warpsum(v[i] * a_dst1[i * 32 + lane]);
        if (!lane) g_d1c[row * 4 + i] = d;
    }
    float fs = 0.f, fd = 0.f;
#pragma unroll
    for (int i = 0; i < 4; i++) {
        fs += v[i] * a_feat[i * 32 + lane];
        fd += v[i] * a_feat[128 + i * 32 + lane];
    }
    fs = warpsum(fs); fd = warpsum(fd);
    if (!lane) { g_fsc[row] = fs; g_fdc[row] = fd; }
}

// ---------------- GAT1: per-group softmax + aggregation + edges_weights ------
__global__ void __launch_bounds__(128) gat1(
    const float* __restrict__ counts_f, const int* __restrict__ offs,
    const int* __restrict__ edges, int T, float* __restrict__ out_ew) {
    int g = blockIdx.x;
    int tid = threadIdx.x, lane = tid & 31, warp = tid >> 5;
    int base = offs[g];
    int cnt = (int)(counts_f[g] + 0.5f);
    int E2 = 2 * T;
    __shared__ float s_alpha[32][4];
    int head = warp;
    float d1 = g_d1c[g * 4 + head];
    float m = -1e30f;
    for (int t = lane; t < cnt; t += 32) {
        float e = lrelu02(g_s1n[(size_t)(base + t) * 4 + head] + d1);
        s_alpha[t][head] = e;
        m = fmaxf(m, e);
    }
    m = warpmax(m);
    float ssum = 0.f;
    for (int t = lane; t < cnt; t += 32) {
        float ex = expf(s_alpha[t][head] - m);
        s_alpha[t][head] = ex;
        ssum += ex;
    }
    ssum = warpsum(ssum);
    float inv = 1.f / (ssum + 1e-16f);
    for (int t = lane; t < cnt; t += 32) s_alpha[t][head] *= inv;
    __syncthreads();
    // x at center g (128 floats)
    int h4 = tid >> 5;
    float acc = 0.f;
    for (int t = 0; t < cnt; t++)
        acc += s_alpha[t][h4] * g_hn[(size_t)(base + t) * 128 + tid];
    g_xc[(size_t)g * 128 + tid] = acc;
    // edges_weights
    if (tid < cnt) {
        int t = tid;
        int ei = base + t;             // first-half edge index
        float am = 0.25f * (s_alpha[t][0] + s_alpha[t][1] + s_alpha[t][2] + s_alpha[t][3]);
        float a2 = sigm(g_fsn[ei] + g_fdc[g]);
        float4 r1 = make_float4((float)edges[ei], (float)edges[E2 + ei], am, a2);
        *(float4*)(out_ew + (size_t)ei * 4) = r1;
        int ej = T + ei;               // second-half edge index
        float a2b = sigm(g_fsc[g] + g_fdn[ei]);
        float4 r2 = make_float4((float)edges[ej], (float)edges[E2 + ej], 1.0f, a2b);
        *(float4*)(out_ew + (size_t)ej * 4) = r2;
    }
}

// ---------------- h2 scalars: s2 = h2·a_src2, d2 = h2·a_dst2 -----------------
__global__ void h2_scalars(const float* __restrict__ a_src2,
                           const float* __restrict__ a_dst2) {
    int row = blockIdx.x * 4 + (threadIdx.x >> 5);
    if (row >= BB) return;
    int lane = threadIdx.x & 31;
    const float* h = g_h2 + (size_t)row * 128;
    float s = 0.f, d = 0.f;
#pragma unroll
    for (int i = 0; i < 4; i++) {
        float v = h[lane + 32 * i];
        s += v * a_src2[lane + 32 * i];
        d += v * a_dst2[lane + 32 * i];
    }
    s = warpsum(s); d = warpsum(d);
    if (!lane) { g_s2[row] = s; g_d2[row] = d; }
}

// ---------------- VT graph softmax (random topology, atomics) ----------------
__global__ void vt_pass1(const int* __restrict__ evt) {
    int i = blockIdx.x * blockDim.x + threadIdx.x;
    if (i >= EVT) return;
    int sv = evt[i], dv = evt[EVT + i];
    float e = lrelu02(g_s2[sv] + g_d2[dv]);
    g_e2v[i] = e;
    atomicMaxFloat(&g_vmax[dv], e);
}
__global__ void vt_pass2(const int* __restrict__ evt) {
    int i = blockIdx.x * blockDim.x + threadIdx.x;
    if (i >= EVT) return;
    int dv = evt[EVT + i];
    float ex = expf(g_e2v[i] - g_vmax[dv]);
    g_e2v[i] = ex;
    atomicAdd(&g_vsum[dv], ex);
}
__global__ void __launch_bounds__(128) vt_pass3(const int* __restrict__ evt,
                                                float* __restrict__ out_alpha,
                                                float* __restrict__ out_xn) {
    int i = blockIdx.x;
    int sv = evt[i], dv = evt[EVT + i];
    float alpha = g_e2v[i] / (g_vsum[dv] + 1e-16f);
    if (threadIdx.x == 0) out_alpha[i] = alpha;
    atomicAdd(&out_xn[(size_t)dv * 128 + threadIdx.x],
              alpha * g_h2[(size_t)sv * 128 + threadIdx.x]);
}

// ---------------- host launcher ----------------------------------------------
extern "C" void kernel_launch(void* const* d_in, const int* in_sizes, int n_in,
                              void* d_out, int out_size) {
    const float* c_in    = (const float*)d_in[0];
    const float* nb_in   = (const float*)d_in[1];
    const float* counts  = (const float*)d_in[2];
    const float* Wq_c    = (const float*)d_in[3];
    const float* Wk_c    = (const float*)d_in[4];
    const float* Wq_n    = (const float*)d_in[5];
    const float* Wk_n    = (const float*)d_in[6];
    const float* W1      = (const float*)d_in[7];
    const float* a_src1  = (const float*)d_in[8];
    const float* a_dst1  = (const float*)d_in[9];
    const float* a_feat  = (const float*)d_in[10];
    const float* W2      = (const float*)d_in[11];
    const float* a_src2  = (const float*)d_in[12];
    const float* a_dst2  = (const float*)d_in[13];
    const int*   seg     = (const int*)d_in[14];
    // d_in[15] centre_pos, d_in[16] neighb_pos: implied by contiguous layout
    const int*   offs    = (const int*)d_in[17];
    const int*   edges   = (const int*)d_in[18];
    const int*   evt     = (const int*)d_in[19];
    int T = in_sizes[1] / GG;

    float* out = (float*)d_out;
    float* out_xn   = out;                              // (B,128)
    float* out_gate = out_xn + (size_t)BB * EMBD;       // (B,256)
    float* out_attn = out_gate + (size_t)BB * GG;       // (B,256)
    float* out_ne   = out_attn + (size_t)BB * GG;       // (B,256)
    float* out_nein = out_ne + (size_t)BB * GG;         // (B,256)
    float* out_ew   = out_nein + (size_t)BB * GG;       // (2T,4)
    float* out_avt  = out_ew + (size_t)8 * T;           // (Evt,)

    float *p_w, *p_ck, *p_M1, *p_cadj, *p_nadj, *p_hn, *p_hc, *p_xc, *p_h2;
    cudaGetSymbolAddress((void**)&p_w, g_w);
    cudaGetSymbolAddress((void**)&p_ck, g_ck);
    cudaGetSymbolAddress((void**)&p_M1, g_M1);
    cudaGetSymbolAddress((void**)&p_cadj, g_cadj);
    cudaGetSymbolAddress((void**)&p_nadj, g_nadj);
    cudaGetSymbolAddress((void**)&p_hn, g_hn);
    cudaGetSymbolAddress((void**)&p_hc, g_hc);
    cudaGetSymbolAddress((void**)&p_xc, g_xc);
    cudaGetSymbolAddress((void**)&p_h2, g_h2);

    int tilesT = (T + 127) / 128;

    init_kernel<<<(BB * EMBD + 255) / 256, 256>>>(out_xn);
    compute_M1<<<GG, 256>>>(Wq_c, Wk_c);

    // w = c @ M1  AND  ck = c @ Wk_n in one launch (8192 x 256 x 256 each)
    sgemm_db_dualB<<<dim3(2, BB / 128, 2), 256>>>(c_in, p_M1, Wk_n, p_w, p_ck,
                                                  BB, 256, 256);

    stageA<<<BB, 128>>>(c_in, nb_in, counts, offs, out_gate, out_nein);

    // n_adj = n * tanh((n@Wq_n) * ck[seg]) + attn_all     (T x 256 x 256)
    sgemm_db_gate<<<dim3(2, tilesT), 256>>>(nb_in, Wq_n, p_nadj, p_ck,
                                            seg, offs, out_attn, T);
    segmean_nadj<<<BB, 128>>>(counts, offs, out_ne);

    // h = node_attr @ W1: neighbor rows + center rows in one launch
    sgemm_db_dualA<<<dim3(1, tilesT + BB / 128), 256>>>(
        p_nadj, p_cadj, W1, p_hn, p_hc, T, BB, tilesT, 128, 256);

    node_scalars_n<<<(T + 3) / 4, 128>>>(a_src1, a_feat, T);
    node_scalars_c<<<BB / 4, 128>>>(a_dst1, a_feat);

    gat1<<<BB, 128>>>(counts, offs, edges, T, out_ew);

    // h2 = xc @ W2     (8192 x 128 x 128)
    sgemm_db<<<dim3(1, BB / 128), 256>>>(p_xc, W2, p_h2, BB, 128, 128);
    h2_scalars<<<BB / 4, 128>>>(a_src2, a_dst2);

    vt_pass1<<<(EVT + 255) / 256, 256>>>(evt);
    vt_pass2<<<(EVT + 255) / 256, 256>>>(evt);
    vt_pass3<<<EVT, 128>>>(evt, out_avt, out_xn);
}

// round 5
// speedup vs baseline: 1.3733x; 1.1530x over previous
#include <cuda_runtime.h>
#include <cuda_bf16.h>
#include <math.h>
#include <stdint.h>

#define BB 8192
#define GG 256
#define EMBD 128
#define NHEAD 4
#define EVT 65536
#define TMAXN 196608  /* 8192 * 24 (counts in [8,24]) */

// ---------------- scratch (static device globals; no runtime allocation) ----
__device__ float g_w[BB * GG];
__device__ float g_ck[BB * GG];
__device__ float g_cadj[BB * GG];
__device__ float g_M1[GG * GG];
__device__ float g_nadj[(size_t)TMAXN * GG];
__device__ float g_hn[(size_t)TMAXN * EMBD];
__device__ float g_hc[BB * EMBD];
__device__ float g_xc[BB * EMBD];
__device__ float g_h2[BB * EMBD];
__device__ float g_s1n[(size_t)TMAXN * NHEAD];
__device__ float g_d1c[BB * NHEAD];
__device__ float g_fsn[TMAXN];
__device__ float g_fdn[TMAXN];
__device__ float g_fsc[BB];
__device__ float g_fdc[BB];
__device__ float g_s2[BB];
__device__ float g_d2[BB];
__device__ float g_e2v[EVT];
__device__ float g_vmax[BB];
__device__ float g_vsum[BB];
// bf16 split operands
__device__ __nv_bfloat16 g_nh[(size_t)TMAXN * GG];      // nb_in hi
__device__ __nv_bfloat16 g_nl[(size_t)TMAXN * GG];      // nb_in lo
__device__ __nv_bfloat16 g_nadjh[(size_t)TMAXN * GG];
__device__ __nv_bfloat16 g_nadjl[(size_t)TMAXN * GG];
__device__ __nv_bfloat16 g_cadjh[BB * GG];
__device__ __nv_bfloat16 g_cadjl[BB * GG];
__device__ __nv_bfloat16 g_Bqh[GG * GG];   // Wq_n^T hi  [n][k]
__device__ __nv_bfloat16 g_Bql[GG * GG];   // Wq_n^T lo
__device__ __nv_bfloat16 g_B1h[EMBD * GG]; // W1^T hi    [n][k]
__device__ __nv_bfloat16 g_B1l[EMBD * GG]; // W1^T lo

// ---------------- helpers ---------------------------------------------------
__device__ __forceinline__ float warpsum(float v) {
#pragma unroll
    for (int o = 16; o; o >>= 1) v += __shfl_xor_sync(0xffffffffu, v, o);
    return v;
}
__device__ __forceinline__ float warpmax(float v) {
#pragma unroll
    for (int o = 16; o; o >>= 1) v = fmaxf(v, __shfl_xor_sync(0xffffffffu, v, o));
    return v;
}
__device__ __forceinline__ void atomicMaxFloat(float* addr, float value) {
    if (value >= 0.f) atomicMax((int*)addr, __float_as_int(value));
    else              atomicMin((unsigned int*)addr, __float_as_uint(value));
}
__device__ __forceinline__ float lrelu02(float x) { return x > 0.f ? x : 0.2f * x; }
__device__ __forceinline__ float sigm(float x) { return 1.f / (1.f + expf(-x)); }

__device__ __forceinline__ uint32_t smem_u32(const void* p) {
    uint32_t a;
    asm("{ .reg .u64 t; cvta.to.shared.u64 t, %1; cvt.u32.u64 %0, t; }"
        : "=r"(a) : "l"(p));
    return a;
}

// split fp32 pair -> (hi bf16x2, lo bf16x2)
__device__ __forceinline__ void bsplit2(float x, float y, uint32_t& h, uint32_t& l) {
    unsigned short hx = __bfloat16_as_ushort(__float2bfloat16(x));
    unsigned short hy = __bfloat16_as_ushort(__float2bfloat16(y));
    float rx = x - __bfloat162float(__ushort_as_bfloat16(hx));
    float ry = y - __bfloat162float(__ushort_as_bfloat16(hy));
    unsigned short lx = __bfloat16_as_ushort(__float2bfloat16(rx));
    unsigned short ly = __bfloat16_as_ushort(__float2bfloat16(ry));
    h = (uint32_t)hx | ((uint32_t)hy << 16);
    l = (uint32_t)lx | ((uint32_t)ly << 16);
}

// ---------------- HMMA primitives --------------------------------------------
__device__ __forceinline__ void ldsm_x4(uint32_t addr, uint32_t& r0, uint32_t& r1,
                                        uint32_t& r2, uint32_t& r3) {
    asm volatile("ldmatrix.sync.aligned.m8n8.x4.shared.b16 {%0,%1,%2,%3}, [%4];"
                 : "=r"(r0), "=r"(r1), "=r"(r2), "=r"(r3) : "r"(addr));
}
__device__ __forceinline__ void mma_bf16(float* c, const uint32_t* a,
                                         uint32_t b0, uint32_t b1) {
    asm volatile(
        "mma.sync.aligned.m16n8k16.row.col.f32.bf16.bf16.f32 "
        "{%0,%1,%2,%3}, {%4,%5,%6,%7}, {%8,%9}, {%0,%1,%2,%3};"
        : "+f"(c[0]), "+f"(c[1]), "+f"(c[2]), "+f"(c[3])
        : "r"(a[0]), "r"(a[1]), "r"(a[2]), "r"(a[3]), "r"(b0), "r"(b1));
}

// stage 128 rows x 32B (16 bf16) of a [rows][256]-bf16 matrix into smem
// with 48B row stride (conflict-free for ldmatrix). Zero-fill beyond M.
__device__ __forceinline__ void stage_tile(const __nv_bfloat16* __restrict__ src,
                                           int row0, int M, int k0,
                                           __nv_bfloat16* dst, int tid) {
#pragma unroll
    for (int s = 0; s < 2; s++) {
        int idx = tid + s * 128;
        int row = idx >> 1, half = idx & 1;
        int4 v = make_int4(0, 0, 0, 0);
        if (row0 + row < M)
            v = *(const int4*)((const uint8_t*)src +
                               (size_t)(row0 + row) * 512 + (size_t)(k0 * 2 + half * 16));
        *(int4*)((uint8_t*)dst + row * 48 + half * 16) = v;
    }
}

// mainloop: C(128x128) += [Ah|Ah|Al](row0..) x [Bh|Bl|Bh]^T(col0..), K=256 per product
#define HMMA_MAINLOOP(AH_, AL_, BH_, BL_, M_, row0_, col0_)                    \
    {                                                                          \
        const int lane_ = tid & 31, w_ = tid >> 5;                             \
        const int wr_ = w_ >> 1, wc_ = w_ & 1;                                 \
        const uint32_t aoff_ =                                                 \
            (uint32_t)((wr_ * 64 + (lane_ & 15)) * 48 + (lane_ >> 4) * 16);    \
        const uint32_t boff_ =                                                 \
            (uint32_t)((wc_ * 64 + (lane_ & 15)) * 48 + (lane_ >> 4) * 16);    \
        int buf = 0;                                                           \
        stage_tile(AH_, row0_, M_, 0, &sA[0][0], tid);                         \
        stage_tile(BH_, col0_, 1 << 30, 0, &sB[0][0], tid);                    \
        __syncthreads();                                                       \
        for (int it = 0; it < 48; it++) {                                      \
            if (it + 1 < 48) {                                                 \
                int prod = (it + 1) >> 4, k0 = ((it + 1) & 15) * 16;           \
                stage_tile(prod == 2 ? (AL_) : (AH_), row0_, M_, k0,           \
                           &sA[buf ^ 1][0], tid);                              \
                stage_tile(prod == 1 ? (BL_) : (BH_), col0_, 1 << 30, k0,      \
                           &sB[buf ^ 1][0], tid);                              \
            }                                                                  \
            uint32_t aBase = smem_u32(&sA[buf][0]) + aoff_;                    \
            uint32_t bBase = smem_u32(&sB[buf][0]) + boff_;                    \
            uint32_t afr[4][4], bfr[4][4];                                     \
            _Pragma("unroll")                                                  \
            for (int rt = 0; rt < 4; rt++)                                     \
                ldsm_x4(aBase + rt * 768, afr[rt][0], afr[rt][1],              \
                        afr[rt][2], afr[rt][3]);                               \
            _Pragma("unroll")                                                  \
            for (int cp = 0; cp < 4; cp++)                                     \
                ldsm_x4(bBase + cp * 768, bfr[cp][0], bfr[cp][1],              \
                        bfr[cp][2], bfr[cp][3]);                               \
            _Pragma("unroll")                                                  \
            for (int rt = 0; rt < 4; rt++)                                     \
                _Pragma("unroll")                                              \
                for (int cp = 0; cp < 4; cp++) {                               \
                    mma_bf16(acc[rt][2 * cp],     afr[rt], bfr[cp][0], bfr[cp][2]); \
                    mma_bf16(acc[rt][2 * cp + 1], afr[rt], bfr[cp][1], bfr[cp][3]); \
                }                                                              \
            __syncthreads();                                                   \
            buf ^= 1;                                                          \
        }                                                                      \
    }

// ---------------- B prep: transposed bf16 splits ------------------------------
__global__ void prep_B_gate(const float* __restrict__ Wq_n) {
    int idx = blockIdx.x * 256 + threadIdx.x;     // 65536
    int k = idx >> 8, n = idx & 255;
    float x = Wq_n[k * 256 + n];
    __nv_bfloat16 h = __float2bfloat16(x);
    float r = x - __bfloat162float(h);
    g_Bqh[n * 256 + k] = h;
    g_Bql[n * 256 + k] = __float2bfloat16(r);
}
__global__ void prep_B_w1(const float* __restrict__ W1) {
    int idx = blockIdx.x * 256 + threadIdx.x;     // 32768
    int k = idx >> 7, n = idx & 127;
    float x = W1[k * 128 + n];
    __nv_bfloat16 h = __float2bfloat16(x);
    float r = x - __bfloat162float(h);
    g_B1h[n * 256 + k] = h;
    g_B1l[n * 256 + k] = __float2bfloat16(r);
}

// ---------------- A split: nb_in -> g_nh/g_nl --------------------------------
__global__ void conv_split(const float4* __restrict__ src, int n4) {
    int i = blockIdx.x * 256 + threadIdx.x;
    if (i >= n4) return;
    float4 v = src[i];
    uint32_t h0, l0, h1, l1;
    bsplit2(v.x, v.y, h0, l0);
    bsplit2(v.z, v.w, h1, l1);
    uint32_t* ph = (uint32_t*)g_nh;
    uint32_t* pl = (uint32_t*)g_nl;
    ph[i * 2] = h0; ph[i * 2 + 1] = h1;
    pl[i * 2] = l0; pl[i * 2 + 1] = l1;
}

// ================= HMMA GEMM 1: gate ==========================================
__global__ void __launch_bounds__(128) hmma_gate(
    const float* __restrict__ Afp, const float* __restrict__ ck,
    const int* __restrict__ seg, const int* __restrict__ offs,
    float* __restrict__ nadj, float* __restrict__ out_attn, int M) {
    __shared__ __align__(16) __nv_bfloat16 sA[2][128 * 24];
    __shared__ __align__(16) __nv_bfloat16 sB[2][128 * 24];
    const int tid = threadIdx.x;
    const int row0 = blockIdx.y * 128, col0 = blockIdx.x * 128;
    float acc[4][8][4] = {};
    HMMA_MAINLOOP(g_nh, g_nl, g_Bqh, g_Bql, M, row0, col0);

    const int lane = tid & 31, w = tid >> 5, wr = w >> 1, wc = w & 1;
    const int g = lane >> 2, q = lane & 3;
#pragma unroll
    for (int rt = 0; rt < 4; rt++) {
#pragma unroll
        for (int i = 0; i < 2; i++) {
            int er = row0 + wr * 64 + rt * 16 + g + i * 8;
            if (er >= M) continue;
            int sg = seg[er];
            bool first = (offs[sg] == er);
            const float* ckrow = ck + (size_t)sg * 256;
            const float* arow = Afp + (size_t)er * 256;
            float* nrow = nadj + (size_t)er * 256;
#pragma unroll
            for (int ct = 0; ct < 8; ct++) {
                int c = col0 + wc * 64 + ct * 8 + q * 2;
                float2 ckv = *(const float2*)(ckrow + c);
                float2 av = *(const float2*)(arow + c);
                float g0 = tanhf(acc[rt][ct][i * 2 + 0] * ckv.x);
                float g1 = tanhf(acc[rt][ct][i * 2 + 1] * ckv.y);
                float2 nj = make_float2(av.x * g0, av.y * g1);
                *(float2*)(nrow + c) = nj;
                uint32_t hh, ll;
                bsplit2(nj.x, nj.y, hh, ll);
                *(uint32_t*)((uint8_t*)g_nadjh + (size_t)er * 512 + c * 2) = hh;
                *(uint32_t*)((uint8_t*)g_nadjl + (size_t)er * 512 + c * 2) = ll;
                if (first)
                    *(float2*)(out_attn + (size_t)sg * 256 + c) = make_float2(g0, g1);
            }
        }
    }
}

// ================= HMMA GEMM 2: [nadj; cadj] @ W1 =============================
__global__ void __launch_bounds__(128) hmma_w1(
    float* __restrict__ C0, float* __restrict__ C1,
    int M0, int M1, int tiles0) {
    __shared__ __align__(16) __nv_bfloat16 sA[2][128 * 24];
    __shared__ __align__(16) __nv_bfloat16 sB[2][128 * 24];
    const int tid = threadIdx.x;
    int t = blockIdx.y;
    const __nv_bfloat16 *Ah, *Al;
    float* C; int M, row0;
    if (t < tiles0) { Ah = g_nadjh; Al = g_nadjl; C = C0; M = M0; row0 = t * 128; }
    else            { Ah = g_cadjh; Al = g_cadjl; C = C1; M = M1; row0 = (t - tiles0) * 128; }
    float acc[4][8][4] = {};
    HMMA_MAINLOOP(Ah, Al, g_B1h, g_B1l, M, row0, 0);

    const int lane = tid & 31, w = tid >> 5, wr = w >> 1, wc = w & 1;
    const int g = lane >> 2, q = lane & 3;
#pragma unroll
    for (int rt = 0; rt < 4; rt++) {
#pragma unroll
        for (int i = 0; i < 2; i++) {
            int er = row0 + wr * 64 + rt * 16 + g + i * 8;
            if (er >= M) continue;
            float* crow = C + (size_t)er * 128;
#pragma unroll
            for (int ct = 0; ct < 8; ct++) {
                int c = wc * 64 + ct * 8 + q * 2;
                *(float2*)(crow + c) = make_float2(acc[rt][ct][i * 2 + 0],
                                                   acc[rt][ct][i * 2 + 1]);
            }
        }
    }
}

// ---------------- init ------------------------------------------------------
__global__ void init_kernel(float* __restrict__ out_xn) {
    int i = blockIdx.x * blockDim.x + threadIdx.x;
    if (i < BB * EMBD) out_xn[i] = 0.f;
    if (i < BB) { g_vmax[i] = -1e30f; g_vsum[i] = 0.f; }
}

// ---------------- M1 = Wq_c @ Wk_c^T  ----------------------------------------
__global__ void compute_M1(const float* __restrict__ Wq_c,
                           const float* __restrict__ Wk_c) {
    int p = blockIdx.x;
    int tid = threadIdx.x, lane = tid & 31, warp = tid >> 5;
    __shared__ float sq[128];
    if (tid < 128) sq[tid] = Wq_c[p * 128 + tid];
    __syncthreads();
    for (int k = warp; k < 256; k += 8) {
        const float* row = Wk_c + (size_t)k * 128;
        float acc = 0.f;
#pragma unroll
        for (int i = 0; i < 4; i++) acc += row[lane + 32 * i] * sq[lane + 32 * i];
        acc = warpsum(acc);
        if (!lane) g_M1[p * 256 + k] = acc;
    }
}

// ============ double-buffered FFMA SGEMM (small GEMMs) =======================
#define GEMM_MAINLOOP(A_, B_, M_, N_, K_, row0_, col0_)                        \
    float acc[8][8] = {};                                                      \
    {                                                                          \
        const int tid = threadIdx.x;                                          \
        const int tx = tid & 15, ty = tid >> 4;                               \
        const int ar0 = tid >> 2;                                              \
        const int ar1 = ar0 + 64;                                              \
        const int ac  = (tid & 3) * 4;                                         \
        const int br0 = tid >> 5;                                              \
        const int br1 = br0 + 8;                                               \
        const int bc  = (tid & 31) * 4;                                        \
        const bool ok0 = (row0_ + ar0) < (M_);                                 \
        const bool ok1 = (row0_ + ar1) < (M_);                                 \
        const float* Ap0 = (A_) + (size_t)(row0_ + ar0) * (K_) + ac;          \
        const float* Ap1 = (A_) + (size_t)(row0_ + ar1) * (K_) + ac;          \
        const float* Bp0 = (B_) + (size_t)br0 * (N_) + col0_ + bc;            \
        const float* Bp1 = (B_) + (size_t)br1 * (N_) + col0_ + bc;            \
        float4 ga0 = ok0 ? *(const float4*)(Ap0) : make_float4(0,0,0,0);      \
        float4 ga1 = ok1 ? *(const float4*)(Ap1) : make_float4(0,0,0,0);      \
        float4 gb0 = *(const float4*)(Bp0);                                   \
        float4 gb1 = *(const float4*)(Bp1);                                   \
        int buf = 0;                                                           \
        As[0][ac+0][ar0]=ga0.x; As[0][ac+1][ar0]=ga0.y;                        \
        As[0][ac+2][ar0]=ga0.z; As[0][ac+3][ar0]=ga0.w;                        \
        As[0][ac+0][ar1]=ga1.x; As[0][ac+1][ar1]=ga1.y;                        \
        As[0][ac+2][ar1]=ga1.z; As[0][ac+3][ar1]=ga1.w;                        \
        *(float4*)&Bs[0][br0][bc] = gb0;                                       \
        *(float4*)&Bs[0][br1][bc] = gb1;                                       \
        __syncthreads();                                                       \
        for (int k0 = 16; k0 < (K_); k0 += 16) {                               \
            ga0 = ok0 ? *(const float4*)(Ap0 + k0) : make_float4(0,0,0,0);    \
            ga1 = ok1 ? *(const float4*)(Ap1 + k0) : make_float4(0,0,0,0);    \
            gb0 = *(const float4*)(Bp0 + (size_t)k0 * (N_));                  \
            gb1 = *(const float4*)(Bp1 + (size_t)k0 * (N_));                  \
            _Pragma("unroll")                                                  \
            for (int kk = 0; kk < 16; kk++) {                                  \
                float a[8], b[8];                                              \
                _Pragma("unroll")                                              \
                for (int i = 0; i < 8; i++) a[i] = As[buf][kk][ty*8+i];        \
                _Pragma("unroll")                                              \
                for (int j = 0; j < 8; j++) b[j] = Bs[buf][kk][tx*8+j];        \
                _Pragma("unroll")                                              \
                for (int i = 0; i < 8; i++)                                    \
                    _Pragma("unroll")                                          \
                    for (int j = 0; j < 8; j++) acc[i][j] += a[i]*b[j];        \
            }                                                                  \
            int nb = buf ^ 1;                                                  \
            As[nb][ac+0][ar0]=ga0.x; As[nb][ac+1][ar0]=ga0.y;                  \
            As[nb][ac+2][ar0]=ga0.z; As[nb][ac+3][ar0]=ga0.w;                  \
            As[nb][ac+0][ar1]=ga1.x; As[nb][ac+1][ar1]=ga1.y;                  \
            As[nb][ac+2][ar1]=ga1.z; As[nb][ac+3][ar1]=ga1.w;                  \
            *(float4*)&Bs[nb][br0][bc] = gb0;                                  \
            *(float4*)&Bs[nb][br1][bc] = gb1;                                  \
            __syncthreads();                                                   \
            buf = nb;                                                          \
        }                                                                      \
        _Pragma("unroll")                                                      \
        for (int kk = 0; kk < 16; kk++) {                                      \
            float a[8], b[8];                                                  \
            _Pragma("unroll")                                                  \
            for (int i = 0; i < 8; i++) a[i] = As[buf][kk][ty*8+i];            \
            _Pragma("unroll")                                                  \
            for (int j = 0; j < 8; j++) b[j] = Bs[buf][kk][tx*8+j];            \
            _Pragma("unroll")                                                  \
            for (int i = 0; i < 8; i++)                                        \
                _Pragma("unroll")                                              \
                for (int j = 0; j < 8; j++) acc[i][j] += a[i]*b[j];            \
        }                                                                      \
    }

__global__ void __launch_bounds__(256, 2) sgemm_db(
    const float* __restrict__ A, const float* __restrict__ Bm,
    float* __restrict__ C, int M, int N, int K) {
    __shared__ float As[2][16][132];
    __shared__ float Bs[2][16][128];
    int row0 = blockIdx.y * 128, col0 = blockIdx.x * 128;
    GEMM_MAINLOOP(A, Bm, M, N, K, row0, col0);
    int tx = threadIdx.x & 15, ty = threadIdx.x >> 4;
#pragma unroll
    for (int i = 0; i < 8; i++) {
        int r = row0 + ty * 8 + i;
        if (r >= M) break;
#pragma unroll
        for (int j = 0; j < 8; j += 4)
            *(float4*)(C + (size_t)r * N + col0 + tx * 8 + j) =
                make_float4(acc[i][j], acc[i][j+1], acc[i][j+2], acc[i][j+3]);
    }
}

__global__ void __launch_bounds__(256, 2) sgemm_db_dualB(
    const float* __restrict__ A,
    const float* __restrict__ B0, const float* __restrict__ B1,
    float* __restrict__ C0, float* __restrict__ C1, int M, int N, int K) {
    __shared__ float As[2][16][132];
    __shared__ float Bs[2][16][128];
    const float* Bm = blockIdx.z ? B1 : B0;
    float* C = blockIdx.z ? C1 : C0;
    int row0 = blockIdx.y * 128, col0 = blockIdx.x * 128;
    GEMM_MAINLOOP(A, Bm, M, N, K, row0, col0);
    int tx = threadIdx.x & 15, ty = threadIdx.x >> 4;
#pragma unroll
    for (int i = 0; i < 8; i++) {
        int r = row0 + ty * 8 + i;
        if (r >= M) break;
#pragma unroll
        for (int j = 0; j < 8; j += 4)
            *(float4*)(C + (size_t)r * N + col0 + tx * 8 + j) =
                make_float4(acc[i][j], acc[i][j+1], acc[i][j+2], acc[i][j+3]);
    }
}

// ---------------- stage A: per-group cross-attention (center) ----------------
__global__ void __launch_bounds__(128) stageA(
    const float* __restrict__ cin, const float* __restrict__ nin,
    const float* __restrict__ counts_f, const int* __restrict__ offs,
    float* __restrict__ out_gate, float* __restrict__ out_nein) {
    int g = blockIdx.x;
    int tid = threadIdx.x, lane = tid & 31, warp = tid >> 5;
    int base = offs[g];
    int cnt = (int)(counts_f[g] + 0.5f);
    __shared__ float s_w[256];
    __shared__ float s_attn[32];
    s_w[tid] = g_w[(size_t)g * 256 + tid];
    s_w[tid + 128] = g_w[(size_t)g * 256 + 128 + tid];
    __syncthreads();
    for (int t = warp; t < cnt; t += 4) {
        const float* row = nin + (size_t)(base + t) * 256;
        float acc = 0.f;
#pragma unroll
        for (int i = 0; i < 8; i++) acc += row[lane + 32 * i] * s_w[lane + 32 * i];
        acc = warpsum(acc);
        if (!lane) s_attn[t] = acc * 0.08838834764831845f;
    }
    __syncthreads();
    if (tid == 0) {
        float m = -1e30f;
        for (int t = 0; t < cnt; t++) m = fmaxf(m, s_attn[t]);
        float s = 0.f;
        for (int t = 0; t < cnt; t++) { float e = expf(s_attn[t] - m); s_attn[t] = e; s += e; }
        float inv = 1.f / (s + 1e-16f);
        for (int t = 0; t < cnt; t++) s_attn[t] *= inv;
    }
    __syncthreads();
    float acc0 = 0.f, acc1 = 0.f, sum0 = 0.f, sum1 = 0.f;
    for (int t = 0; t < cnt; t++) {
        const float* row = nin + (size_t)(base + t) * 256;
        float v0 = row[tid], v1 = row[tid + 128];
        float a = s_attn[t];
        acc0 += a * v0; acc1 += a * v1;
        sum0 += v0;     sum1 += v1;
    }
    float gate0 = tanhf(acc0), gate1 = tanhf(acc1);
    size_t o = (size_t)g * 256 + tid;
    float c0 = cin[o], c1 = cin[o + 128];
    out_gate[o] = gate0;            out_gate[o + 128] = gate1;
    float ca0 = c0 * gate0, ca1 = c1 * gate1;
    g_cadj[o] = ca0;                g_cadj[o + 128] = ca1;
    // bf16 split of cadj for W1 HMMA GEMM
    __nv_bfloat16 h0 = __float2bfloat16(ca0);
    __nv_bfloat16 h1 = __float2bfloat16(ca1);
    g_cadjh[o] = h0;                g_cadjh[o + 128] = h1;
    g_cadjl[o] = __float2bfloat16(ca0 - __bfloat162float(h0));
    g_cadjl[o + 128] = __float2bfloat16(ca1 - __bfloat162float(h1));
    out_nein[o] = c0 + sum0;        out_nein[o + 128] = c1 + sum1;
}

// ---------------- neighb_expr = segsum(n_adj)/counts -------------------------
__global__ void __launch_bounds__(128) segmean_nadj(
    const float* __restrict__ counts_f, const int* __restrict__ offs,
    float* __restrict__ out_ne) {
    int g = blockIdx.x;
    int tid = threadIdx.x;
    int base = offs[g];
    int cnt = (int)(counts_f[g] + 0.5f);
    float inv = 1.f / counts_f[g];
    float s0 = 0.f, s1 = 0.f;
    for (int t = 0; t < cnt; t++) {
        const float* row = g_nadj + (size_t)(base + t) * 256;
        s0 += row[tid]; s1 += row[tid + 128];
    }
    out_ne[(size_t)g * 256 + tid] = s0 * inv;
    out_ne[(size_t)g * 256 + 128 + tid] = s1 * inv;
}

// ---------------- per-node scalars (neighbors) --------------------------------
__global__ void node_scalars_n(const float* __restrict__ a_src1,
                               const float* __restrict__ a_feat, int T) {
    int row = blockIdx.x * 4 + (threadIdx.x >> 5);
    if (row >= T) return;
    int lane = threadIdx.x & 31;
    const float* h = g_hn + (size_t)row * 128;
    float v[4];
#pragma unroll
    for (int i = 0; i < 4; i++) v[i] = h[lane + 32 * i];
#pragma unroll
    for (int i = 0; i < 4; i++) {
        float s = warpsum(v[i] * a_src1[i * 32 + lane]);
        if (!lane) g_s1n[(size_t)row * 4 + i] = s;
    }
    float fs = 0.f, fd = 0.f;
#pragma unroll
    for (int i = 0; i < 4; i++) {
        fs += v[i] * a_feat[i * 32 + lane];
        fd += v[i] * a_feat[128 + i * 32 + lane];
    }
    fs = warpsum(fs); fd = warpsum(fd);
    if (!lane) { g_fsn[row] = fs; g_fdn[row] = fd; }
}

// ---------------- per-node scalars (centers) ----------------------------------
__global__ void node_scalars_c(const float* __restrict__ a_dst1,
                               const float* __restrict__ a_feat) {
    int row = blockIdx.x * 4 + (threadIdx.x >> 5);
    if (row >= BB) return;
    int lane = threadIdx.x & 31;
    const float* h = g_hc + (size_t)row * 128;
    float v[4];
#pragma unroll
    for (int i = 0; i < 4; i++) v[i] = h[lane + 32 * i];
#pragma unroll
    for (int i = 0; i < 4; i++) {
        float d = warpsum(v[i] * a_dst1[i * 32 + lane]);
        if (!lane) g_d1c[row * 4 + i] = d;
    }
    float fs = 0.f, fd = 0.f;
#pragma unroll
    for (int i = 0; i < 4; i++) {
        fs += v[i] * a_feat[i * 32 + lane];
        fd += v[i] * a_feat[128 + i * 32 + lane];
    }
    fs = warpsum(fs); fd = warpsum(fd);
    if (!lane) { g_fsc[row] = fs; g_fdc[row] = fd; }
}

// ---------------- GAT1 --------------------------------------------------------
__global__ void __launch_bounds__(128) gat1(
    const float* __restrict__ counts_f, const int* __restrict__ offs,
    const int* __restrict__ edges, int T, float* __restrict__ out_ew) {
    int g = blockIdx.x;
    int tid = threadIdx.x, lane = tid & 31, warp = tid >> 5;
    int base = offs[g];
    int cnt = (int)(counts_f[g] + 0.5f);
    int E2 = 2 * T;
    __shared__ float s_alpha[32][4];
    int head = warp;
    float d1 = g_d1c[g * 4 + head];
    float m = -1e30f;
    for (int t = lane; t < cnt; t += 32) {
        float e = lrelu02(g_s1n[(size_t)(base + t) * 4 + head] + d1);
        s_alpha[t][head] = e;
        m = fmaxf(m, e);
    }
    m = warpmax(m);
    float ssum = 0.f;
    for (int t = lane; t < cnt; t += 32) {
        float ex = expf(s_alpha[t][head] - m);
        s_alpha[t][head] = ex;
        ssum += ex;
    }
    ssum = warpsum(ssum);
    float inv = 1.f / (ssum + 1e-16f);
    for (int t = lane; t < cnt; t += 32) s_alpha[t][head] *= inv;
    __syncthreads();
    int h4 = tid >> 5;
    float acc = 0.f;
    for (int t = 0; t < cnt; t++)
        acc += s_alpha[t][h4] * g_hn[(size_t)(base + t) * 128 + tid];
    g_xc[(size_t)g * 128 + tid] = acc;
    if (tid < cnt) {
        int t = tid;
        int ei = base + t;
        float am = 0.25f * (s_alpha[t][0] + s_alpha[t][1] + s_alpha[t][2] + s_alpha[t][3]);
        float a2 = sigm(g_fsn[ei] + g_fdc[g]);
        float4 r1 = make_float4((float)edges[ei], (float)edges[E2 + ei], am, a2);
        *(float4*)(out_ew + (size_t)ei * 4) = r1;
        int ej = T + ei;
        float a2b = sigm(g_fsc[g] + g_fdn[ei]);
        float4 r2 = make_float4((float)edges[ej], (float)edges[E2 + ej], 1.0f, a2b);
        *(float4*)(out_ew + (size_t)ej * 4) = r2;
    }
}

// ---------------- h2 scalars ---------------------------------------------------
__global__ void h2_scalars(const float* __restrict__ a_src2,
                           const float* __restrict__ a_dst2) {
    int row = blockIdx.x * 4 + (threadIdx.x >> 5);
    if (row >= BB) return;
    int lane = threadIdx.x & 31;
    const float* h = g_h2 + (size_t)row * 128;
    float s = 0.f, d = 0.f;
#pragma unroll
    for (int i = 0; i < 4; i++) {
        float v = h[lane + 32 * i];
        s += v * a_src2[lane + 32 * i];
        d += v * a_dst2[lane + 32 * i];
    }
    s = warpsum(s); d = warpsum(d);
    if (!lane) { g_s2[row] = s; g_d2[row] = d; }
}

// ---------------- VT graph softmax ---------------------------------------------
__global__ void vt_pass1(const int* __restrict__ evt) {
    int i = blockIdx.x * blockDim.x + threadIdx.x;
    if (i >= EVT) return;
    int sv = evt[i], dv = evt[EVT + i];
    float e = lrelu02(g_s2[sv] + g_d2[dv]);
    g_e2v[i] = e;
    atomicMaxFloat(&g_vmax[dv], e);
}
__global__ void vt_pass2(const int* __restrict__ evt) {
    int i = blockIdx.x * blockDim.x + threadIdx.x;
    if (i >= EVT) return;
    int dv = evt[EVT + i];
    float ex = expf(g_e2v[i] - g_vmax[dv]);
    g_e2v[i] = ex;
    atomicAdd(&g_vsum[dv], ex);
}
__global__ void __launch_bounds__(128) vt_pass3(const int* __restrict__ evt,
                                                float* __restrict__ out_alpha,
                                                float* __restrict__ out_xn) {
    int i = blockIdx.x;
    int sv = evt[i], dv = evt[EVT + i];
    float alpha = g_e2v[i] / (g_vsum[dv] + 1e-16f);
    if (threadIdx.x == 0) out_alpha[i] = alpha;
    atomicAdd(&out_xn[(size_t)dv * 128 + threadIdx.x],
              alpha * g_h2[(size_t)sv * 128 + threadIdx.x]);
}

// ---------------- host launcher -------------------------------------------------
extern "C" void kernel_launch(void* const* d_in, const int* in_sizes, int n_in,
                              void* d_out, int out_size) {
    const float* c_in    = (const float*)d_in[0];
    const float* nb_in   = (const float*)d_in[1];
    const float* counts  = (const float*)d_in[2];
    const float* Wq_c    = (const float*)d_in[3];
    const float* Wk_c    = (const float*)d_in[4];
    const float* Wq_n    = (const float*)d_in[5];
    const float* Wk_n    = (const float*)d_in[6];
    const float* W1      = (const float*)d_in[7];
    const float* a_src1  = (const float*)d_in[8];
    const float* a_dst1  = (const float*)d_in[9];
    const float* a_feat  = (const float*)d_in[10];
    const float* W2      = (const float*)d_in[11];
    const float* a_src2  = (const float*)d_in[12];
    const float* a_dst2  = (const float*)d_in[13];
    const int*   seg     = (const int*)d_in[14];
    const int*   offs    = (const int*)d_in[17];
    const int*   edges   = (const int*)d_in[18];
    const int*   evt     = (const int*)d_in[19];
    int T = in_sizes[1] / GG;

    float* out = (float*)d_out;
    float* out_xn   = out;
    float* out_gate = out_xn + (size_t)BB * EMBD;
    float* out_attn = out_gate + (size_t)BB * GG;
    float* out_ne   = out_attn + (size_t)BB * GG;
    float* out_nein = out_ne + (size_t)BB * GG;
    float* out_ew   = out_nein + (size_t)BB * GG;
    float* out_avt  = out_ew + (size_t)8 * T;

    float *p_w, *p_ck, *p_M1, *p_nadj, *p_hn, *p_hc, *p_xc, *p_h2;
    cudaGetSymbolAddress((void**)&p_w, g_w);
    cudaGetSymbolAddress((void**)&p_ck, g_ck);
    cudaGetSymbolAddress((void**)&p_M1, g_M1);
    cudaGetSymbolAddress((void**)&p_nadj, g_nadj);
    cudaGetSymbolAddress((void**)&p_hn, g_hn);
    cudaGetSymbolAddress((void**)&p_hc, g_hc);
    cudaGetSymbolAddress((void**)&p_xc, g_xc);
    cudaGetSymbolAddress((void**)&p_h2, g_h2);

    int tilesT = (T + 127) / 128;

    init_kernel<<<(BB * EMBD + 255) / 256, 256>>>(out_xn);
    compute_M1<<<GG, 256>>>(Wq_c, Wk_c);
    prep_B_gate<<<256, 256>>>(Wq_n);
    prep_B_w1<<<128, 256>>>(W1);
    conv_split<<<(T * 64 + 255) / 256, 256>>>((const float4*)nb_in, T * 64);

    // w = c @ M1  AND  ck = c @ Wk_n (FFMA)
    sgemm_db_dualB<<<dim3(2, BB / 128, 2), 256>>>(c_in, p_M1, Wk_n, p_w, p_ck,
                                                  BB, 256, 256);

    stageA<<<BB, 128>>>(c_in, nb_in, counts, offs, out_gate, out_nein);

    // n_adj via HMMA bf16-split GEMM + fused tanh gate epilogue
    hmma_gate<<<dim3(2, tilesT), 128>>>(nb_in, p_ck, seg, offs, p_nadj,
                                        out_attn, T);
    segmean_nadj<<<BB, 128>>>(counts, offs, out_ne);

    // h = [nadj; cadj] @ W1 via HMMA
    hmma_w1<<<dim3(1, tilesT + BB / 128), 128>>>(p_hn, p_hc, T, BB, tilesT);

    node_scalars_n<<<(T + 3) / 4, 128>>>(a_src1, a_feat, T);
    node_scalars_c<<<BB / 4, 128>>>(a_dst1, a_feat);

    gat1<<<BB, 128>>>(counts, offs, edges, T, out_ew);

    // h2 = xc @ W2 (FFMA)
    sgemm_db<<<dim3(1, BB / 128), 256>>>(p_xc, W2, p_h2, BB, 128, 128);
    h2_scalars<<<BB / 4, 128>>>(a_src2, a_dst2);

    vt_pass1<<<(EVT + 255) / 256, 256>>>(evt);
    vt_pass2<<<(EVT + 255) / 256, 256>>>(evt);
    vt_pass3<<<EVT, 128>>>(evt, out_avt, out_xn);
}

// round 6
// speedup vs baseline: 1.4320x; 1.0427x over previous
#include <cuda_runtime.h>
#include <cuda_bf16.h>
#include <math.h>
#include <stdint.h>

#define BB 8192
#define GG 256
#define EMBD 128
#define NHEAD 4
#define EVT 65536
#define TMAXN 196608  /* 8192 * 24 (counts in [8,24]) */

// ---------------- scratch (static device globals) ----------------------------
__device__ float g_w[BB * GG];
__device__ float g_ck[BB * GG];
__device__ float g_M1[GG * GG];
__device__ float g_hn[(size_t)TMAXN * EMBD];
__device__ float g_hc[BB * EMBD];
__device__ float g_xc[BB * EMBD];
__device__ float g_h2[BB * EMBD];
__device__ float g_s1n[(size_t)TMAXN * NHEAD];
__device__ float g_d1c[BB * NHEAD];
__device__ float g_fsn[TMAXN];
__device__ float g_fdn[TMAXN];
__device__ float g_fsc[BB];
__device__ float g_fdc[BB];
__device__ float g_s2[BB];
__device__ float g_d2[BB];
__device__ float g_e2v[EVT];
__device__ float g_vmax[BB];
__device__ float g_vsum[BB];
// bf16 split operands
__device__ __nv_bfloat16 g_nh[(size_t)TMAXN * GG];
__device__ __nv_bfloat16 g_nl[(size_t)TMAXN * GG];
__device__ __nv_bfloat16 g_nadjh[(size_t)TMAXN * GG];
__device__ __nv_bfloat16 g_nadjl[(size_t)TMAXN * GG];
__device__ __nv_bfloat16 g_cadjh[BB * GG];
__device__ __nv_bfloat16 g_cadjl[BB * GG];
__device__ __nv_bfloat16 g_ch[BB * GG];
__device__ __nv_bfloat16 g_cl[BB * GG];
__device__ __nv_bfloat16 g_xch[BB * EMBD];
__device__ __nv_bfloat16 g_xcl[BB * EMBD];
__device__ __nv_bfloat16 g_Bqh[GG * GG];    // Wq_n^T  [n][k]
__device__ __nv_bfloat16 g_Bql[GG * GG];
__device__ __nv_bfloat16 g_B1h[EMBD * GG];  // W1^T    [n][k]
__device__ __nv_bfloat16 g_B1l[EMBD * GG];
__device__ __nv_bfloat16 g_BM1h[GG * GG];   // M1^T    [n][k]
__device__ __nv_bfloat16 g_BM1l[GG * GG];
__device__ __nv_bfloat16 g_BWkh[GG * GG];   // Wk_n^T  [n][k]
__device__ __nv_bfloat16 g_BWkl[GG * GG];
__device__ __nv_bfloat16 g_B2h[EMBD * EMBD];// W2^T    [n][k]
__device__ __nv_bfloat16 g_B2l[EMBD * EMBD];

// ---------------- helpers ----------------------------------------------------
__device__ __forceinline__ float warpsum(float v) {
#pragma unroll
    for (int o = 16; o; o >>= 1) v += __shfl_xor_sync(0xffffffffu, v, o);
    return v;
}
__device__ __forceinline__ float warpmax(float v) {
#pragma unroll
    for (int o = 16; o; o >>= 1) v = fmaxf(v, __shfl_xor_sync(0xffffffffu, v, o));
    return v;
}
__device__ __forceinline__ void atomicMaxFloat(float* addr, float value) {
    if (value >= 0.f) atomicMax((int*)addr, __float_as_int(value));
    else              atomicMin((unsigned int*)addr, __float_as_uint(value));
}
__device__ __forceinline__ float lrelu02(float x) { return x > 0.f ? x : 0.2f * x; }
__device__ __forceinline__ float sigm(float x) { return 1.f / (1.f + expf(-x)); }

__device__ __forceinline__ uint32_t smem_u32(const void* p) {
    uint32_t a;
    asm("{ .reg .u64 t; cvta.to.shared.u64 t, %1; cvt.u32.u64 %0, t; }"
        : "=r"(a) : "l"(p));
    return a;
}
__device__ __forceinline__ void bsplit2(float x, float y, uint32_t& h, uint32_t& l) {
    unsigned short hx = __bfloat16_as_ushort(__float2bfloat16(x));
    unsigned short hy = __bfloat16_as_ushort(__float2bfloat16(y));
    float rx = x - __bfloat162float(__ushort_as_bfloat16(hx));
    float ry = y - __bfloat162float(__ushort_as_bfloat16(hy));
    unsigned short lx = __bfloat16_as_ushort(__float2bfloat16(rx));
    unsigned short ly = __bfloat16_as_ushort(__float2bfloat16(ry));
    h = (uint32_t)hx | ((uint32_t)hy << 16);
    l = (uint32_t)lx | ((uint32_t)ly << 16);
}

// ---------------- HMMA primitives --------------------------------------------
__device__ __forceinline__ void ldsm_x4(uint32_t addr, uint32_t& r0, uint32_t& r1,
                                        uint32_t& r2, uint32_t& r3) {
    asm volatile("ldmatrix.sync.aligned.m8n8.x4.shared.b16 {%0,%1,%2,%3}, [%4];"
                 : "=r"(r0), "=r"(r1), "=r"(r2), "=r"(r3) : "r"(addr));
}
__device__ __forceinline__ void mma_bf16(float* c, const uint32_t* a,
                                         uint32_t b0, uint32_t b1) {
    asm volatile(
        "mma.sync.aligned.m16n8k16.row.col.f32.bf16.bf16.f32 "
        "{%0,%1,%2,%3}, {%4,%5,%6,%7}, {%8,%9}, {%0,%1,%2,%3};"
        : "+f"(c[0]), "+f"(c[1]), "+f"(c[2]), "+f"(c[3])
        : "r"(a[0]), "r"(a[1]), "r"(a[2]), "r"(a[3]), "r"(b0), "r"(b1));
}

// stage 128 rows x 16 bf16 (32B) starting at column k0; 48B smem row stride.
__device__ __forceinline__ void stage_tile(const __nv_bfloat16* __restrict__ src,
                                           int row0, int M, int k0, int rowElems,
                                           __nv_bfloat16* dst, int tid) {
#pragma unroll
    for (int s = 0; s < 2; s++) {
        int idx = tid + s * 128;
        int row = idx >> 1, half = idx & 1;
        int4 v = make_int4(0, 0, 0, 0);
        if (row0 + row < M)
            v = *(const int4*)((const uint8_t*)src +
                               (size_t)(row0 + row) * (rowElems * 2) +
                               (size_t)(k0 * 2 + half * 16));
        *(int4*)((uint8_t*)dst + row * 48 + half * 16) = v;
    }
}

// mainloop: C(128x128) += [Ah|Ah|Al] x [Bh|Bl|Bh]^T, K = KSTEPS_*16 per product
#define HMMA_MAINLOOP(AH_, AL_, BH_, BL_, M_, row0_, col0_, KELA_, KELB_, KSTEPS_) \
    {                                                                          \
        const int lane_ = tid & 31, w_ = tid >> 5;                             \
        const int wr_ = w_ >> 1, wc_ = w_ & 1;                                 \
        const uint32_t aoff_ =                                                 \
            (uint32_t)((wr_ * 64 + (lane_ & 15)) * 48 + (lane_ >> 4) * 16);    \
        const uint32_t boff_ =                                                 \
            (uint32_t)((wc_ * 64 + (lane_ & 15)) * 48 + (lane_ >> 4) * 16);    \
        int buf = 0;                                                           \
        stage_tile(AH_, row0_, M_, 0, KELA_, &sA[0][0], tid);                  \
        stage_tile(BH_, col0_, 1 << 30, 0, KELB_, &sB[0][0], tid);             \
        __syncthreads();                                                       \
        const int nit_ = 3 * (KSTEPS_);                                        \
        for (int it = 0; it < nit_; it++) {                                    \
            if (it + 1 < nit_) {                                               \
                int prod = (it + 1) / (KSTEPS_);                               \
                int k0 = ((it + 1) % (KSTEPS_)) * 16;                          \
                stage_tile(prod == 2 ? (AL_) : (AH_), row0_, M_, k0, KELA_,    \
                           &sA[buf ^ 1][0], tid);                              \
                stage_tile(prod == 1 ? (BL_) : (BH_), col0_, 1 << 30, k0,      \
                           KELB_, &sB[buf ^ 1][0], tid);                       \
            }                                                                  \
            uint32_t aBase = smem_u32(&sA[buf][0]) + aoff_;                    \
            uint32_t bBase = smem_u32(&sB[buf][0]) + boff_;                    \
            uint32_t afr[4][4], bfr[4][4];                                     \
            _Pragma("unroll")                                                  \
            for (int rt = 0; rt < 4; rt++)                                     \
                ldsm_x4(aBase + rt * 768, afr[rt][0], afr[rt][1],              \
                        afr[rt][2], afr[rt][3]);                               \
            _Pragma("unroll")                                                  \
            for (int cp = 0; cp < 4; cp++)                                     \
                ldsm_x4(bBase + cp * 768, bfr[cp][0], bfr[cp][1],              \
                        bfr[cp][2], bfr[cp][3]);                               \
            _Pragma("unroll")                                                  \
            for (int rt = 0; rt < 4; rt++)                                     \
                _Pragma("unroll")                                              \
                for (int cp = 0; cp < 4; cp++) {                               \
                    mma_bf16(acc[rt][2 * cp],     afr[rt], bfr[cp][0], bfr[cp][2]); \
                    mma_bf16(acc[rt][2 * cp + 1], afr[rt], bfr[cp][1], bfr[cp][3]); \
                }                                                              \
            __syncthreads();                                                   \
            buf ^= 1;                                                          \
        }                                                                      \
    }

// ---------------- prep kernels ------------------------------------------------
__global__ void prep_B_gate(const float* __restrict__ Wq_n) {
    int idx = blockIdx.x * 256 + threadIdx.x;     // 65536
    int k = idx >> 8, n = idx & 255;
    float x = Wq_n[k * 256 + n];
    __nv_bfloat16 h = __float2bfloat16(x);
    g_Bqh[n * 256 + k] = h;
    g_Bql[n * 256 + k] = __float2bfloat16(x - __bfloat162float(h));
}
__global__ void prep_B_w1(const float* __restrict__ W1) {
    int idx = blockIdx.x * 256 + threadIdx.x;     // 32768
    int k = idx >> 7, n = idx & 127;
    float x = W1[k * 128 + n];
    __nv_bfloat16 h = __float2bfloat16(x);
    g_B1h[n * 256 + k] = h;
    g_B1l[n * 256 + k] = __float2bfloat16(x - __bfloat162float(h));
}
__global__ void prep_B_M1Wk(const float* __restrict__ Wk_n) {
    int idx = blockIdx.x * 256 + threadIdx.x;     // 65536
    int k = idx >> 8, n = idx & 255;
    float x = g_M1[k * 256 + n];
    __nv_bfloat16 h = __float2bfloat16(x);
    g_BM1h[n * 256 + k] = h;
    g_BM1l[n * 256 + k] = __float2bfloat16(x - __bfloat162float(h));
    float y = Wk_n[k * 256 + n];
    __nv_bfloat16 hy = __float2bfloat16(y);
    g_BWkh[n * 256 + k] = hy;
    g_BWkl[n * 256 + k] = __float2bfloat16(y - __bfloat162float(hy));
}
__global__ void prep_B_w2(const float* __restrict__ W2) {
    int idx = blockIdx.x * 256 + threadIdx.x;     // 16384
    int k = idx >> 7, n = idx & 127;
    float x = W2[k * 128 + n];
    __nv_bfloat16 h = __float2bfloat16(x);
    g_B2h[n * 128 + k] = h;
    g_B2l[n * 128 + k] = __float2bfloat16(x - __bfloat162float(h));
}
__global__ void conv_split(const float4* __restrict__ src,
                           __nv_bfloat16* __restrict__ dh,
                           __nv_bfloat16* __restrict__ dl, int n4) {
    int i = blockIdx.x * 256 + threadIdx.x;
    if (i >= n4) return;
    float4 v = src[i];
    uint32_t h0, l0, h1, l1;
    bsplit2(v.x, v.y, h0, l0);
    bsplit2(v.z, v.w, h1, l1);
    ((uint32_t*)dh)[i * 2] = h0; ((uint32_t*)dh)[i * 2 + 1] = h1;
    ((uint32_t*)dl)[i * 2] = l0; ((uint32_t*)dl)[i * 2 + 1] = l1;
}

// ================= HMMA GEMM: w/ck dual-B =====================================
__global__ void __launch_bounds__(128) hmma_wck(float* __restrict__ Cw,
                                                float* __restrict__ Cck) {
    __shared__ __align__(16) __nv_bfloat16 sA[2][128 * 24];
    __shared__ __align__(16) __nv_bfloat16 sB[2][128 * 24];
    const int tid = threadIdx.x;
    const int row0 = blockIdx.y * 128, col0 = blockIdx.x * 128;
    const __nv_bfloat16* Bh = blockIdx.z ? g_BWkh : g_BM1h;
    const __nv_bfloat16* Bl = blockIdx.z ? g_BWkl : g_BM1l;
    float* C = blockIdx.z ? Cck : Cw;
    float acc[4][8][4] = {};
    HMMA_MAINLOOP(g_ch, g_cl, Bh, Bl, BB, row0, col0, 256, 256, 16);
    const int lane = tid & 31, w = tid >> 5, wr = w >> 1, wc = w & 1;
    const int g = lane >> 2, q = lane & 3;
#pragma unroll
    for (int rt = 0; rt < 4; rt++)
#pragma unroll
        for (int i = 0; i < 2; i++) {
            int er = row0 + wr * 64 + rt * 16 + g + i * 8;
            float* crow = C + (size_t)er * 256;
#pragma unroll
            for (int ct = 0; ct < 8; ct++) {
                int c = col0 + wc * 64 + ct * 8 + q * 2;
                *(float2*)(crow + c) = make_float2(acc[rt][ct][i * 2 + 0],
                                                   acc[rt][ct][i * 2 + 1]);
            }
        }
}

// ================= HMMA GEMM: gate ============================================
__global__ void __launch_bounds__(128) hmma_gate(
    const float* __restrict__ Afp, const float* __restrict__ ck,
    const int* __restrict__ seg, const int* __restrict__ offs,
    float* __restrict__ out_attn, int M) {
    __shared__ __align__(16) __nv_bfloat16 sA[2][128 * 24];
    __shared__ __align__(16) __nv_bfloat16 sB[2][128 * 24];
    const int tid = threadIdx.x;
    const int row0 = blockIdx.y * 128, col0 = blockIdx.x * 128;
    float acc[4][8][4] = {};
    HMMA_MAINLOOP(g_nh, g_nl, g_Bqh, g_Bql, M, row0, col0, 256, 256, 16);
    const int lane = tid & 31, w = tid >> 5, wr = w >> 1, wc = w & 1;
    const int g = lane >> 2, q = lane & 3;
#pragma unroll
    for (int rt = 0; rt < 4; rt++)
#pragma unroll
        for (int i = 0; i < 2; i++) {
            int er = row0 + wr * 64 + rt * 16 + g + i * 8;
            if (er >= M) continue;
            int sg = seg[er];
            bool first = (offs[sg] == er);
            const float* ckrow = ck + (size_t)sg * 256;
            const float* arow = Afp + (size_t)er * 256;
#pragma unroll
            for (int ct = 0; ct < 8; ct++) {
                int c = col0 + wc * 64 + ct * 8 + q * 2;
                float2 ckv = *(const float2*)(ckrow + c);
                float2 av = *(const float2*)(arow + c);
                float g0 = tanhf(acc[rt][ct][i * 2 + 0] * ckv.x);
                float g1 = tanhf(acc[rt][ct][i * 2 + 1] * ckv.y);
                uint32_t hh, ll;
                bsplit2(av.x * g0, av.y * g1, hh, ll);
                *(uint32_t*)((uint8_t*)g_nadjh + (size_t)er * 512 + c * 2) = hh;
                *(uint32_t*)((uint8_t*)g_nadjl + (size_t)er * 512 + c * 2) = ll;
                if (first)
                    *(float2*)(out_attn + (size_t)sg * 256 + c) = make_float2(g0, g1);
            }
        }
}

// ================= HMMA GEMM: [nadj; cadj] @ W1 ===============================
__global__ void __launch_bounds__(128) hmma_w1(
    float* __restrict__ C0, float* __restrict__ C1,
    int M0, int M1, int tiles0) {
    __shared__ __align__(16) __nv_bfloat16 sA[2][128 * 24];
    __shared__ __align__(16) __nv_bfloat16 sB[2][128 * 24];
    const int tid = threadIdx.x;
    int t = blockIdx.y;
    const __nv_bfloat16 *Ah, *Al;
    float* C; int M, row0;
    if (t < tiles0) { Ah = g_nadjh; Al = g_nadjl; C = C0; M = M0; row0 = t * 128; }
    else            { Ah = g_cadjh; Al = g_cadjl; C = C1; M = M1; row0 = (t - tiles0) * 128; }
    float acc[4][8][4] = {};
    HMMA_MAINLOOP(Ah, Al, g_B1h, g_B1l, M, row0, 0, 256, 256, 16);
    const int lane = tid & 31, w = tid >> 5, wr = w >> 1, wc = w & 1;
    const int g = lane >> 2, q = lane & 3;
#pragma unroll
    for (int rt = 0; rt < 4; rt++)
#pragma unroll
        for (int i = 0; i < 2; i++) {
            int er = row0 + wr * 64 + rt * 16 + g + i * 8;
            if (er >= M) continue;
            float* crow = C + (size_t)er * 128;
#pragma unroll
            for (int ct = 0; ct < 8; ct++) {
                int c = wc * 64 + ct * 8 + q * 2;
                *(float2*)(crow + c) = make_float2(acc[rt][ct][i * 2 + 0],
                                                   acc[rt][ct][i * 2 + 1]);
            }
        }
}

// ================= HMMA GEMM: h2 = xc @ W2  (K=128, N=128) ====================
__global__ void __launch_bounds__(128) hmma_h2(float* __restrict__ C) {
    __shared__ __align__(16) __nv_bfloat16 sA[2][128 * 24];
    __shared__ __align__(16) __nv_bfloat16 sB[2][128 * 24];
    const int tid = threadIdx.x;
    const int row0 = blockIdx.y * 128;
    float acc[4][8][4] = {};
    HMMA_MAINLOOP(g_xch, g_xcl, g_B2h, g_B2l, BB, row0, 0, 128, 128, 8);
    const int lane = tid & 31, w = tid >> 5, wr = w >> 1, wc = w & 1;
    const int g = lane >> 2, q = lane & 3;
#pragma unroll
    for (int rt = 0; rt < 4; rt++)
#pragma unroll
        for (int i = 0; i < 2; i++) {
            int er = row0 + wr * 64 + rt * 16 + g + i * 8;
            float* crow = C + (size_t)er * 128;
#pragma unroll
            for (int ct = 0; ct < 8; ct++) {
                int c = wc * 64 + ct * 8 + q * 2;
                *(float2*)(crow + c) = make_float2(acc[rt][ct][i * 2 + 0],
                                                   acc[rt][ct][i * 2 + 1]);
            }
        }
}

// ---------------- init --------------------------------------------------------
__global__ void init_kernel(float* __restrict__ out_xn) {
    int i = blockIdx.x * blockDim.x + threadIdx.x;
    if (i < BB * EMBD) out_xn[i] = 0.f;
    if (i < BB) { g_vmax[i] = -1e30f; g_vsum[i] = 0.f; }
}

// ---------------- M1 = Wq_c @ Wk_c^T  -----------------------------------------
__global__ void compute_M1(const float* __restrict__ Wq_c,
                           const float* __restrict__ Wk_c) {
    int p = blockIdx.x;
    int tid = threadIdx.x, lane = tid & 31, warp = tid >> 5;
    __shared__ float sq[128];
    if (tid < 128) sq[tid] = Wq_c[p * 128 + tid];
    __syncthreads();
    for (int k = warp; k < 256; k += 8) {
        const float* row = Wk_c + (size_t)k * 128;
        float acc = 0.f;
#pragma unroll
        for (int i = 0; i < 4; i++) acc += row[lane + 32 * i] * sq[lane + 32 * i];
        acc = warpsum(acc);
        if (!lane) g_M1[p * 256 + k] = acc;
    }
}

// ---------------- stage A: cross-attention + n/cadj splits --------------------
__global__ void __launch_bounds__(128) stageA(
    const float* __restrict__ cin, const float* __restrict__ nin,
    const float* __restrict__ counts_f, const int* __restrict__ offs,
    float* __restrict__ out_gate, float* __restrict__ out_nein) {
    int g = blockIdx.x;
    int tid = threadIdx.x, lane = tid & 31, warp = tid >> 5;
    int base = offs[g];
    int cnt = (int)(counts_f[g] + 0.5f);
    __shared__ float s_w[256];
    __shared__ float s_attn[32];
    s_w[tid] = g_w[(size_t)g * 256 + tid];
    s_w[tid + 128] = g_w[(size_t)g * 256 + 128 + tid];
    __syncthreads();
    for (int t = warp; t < cnt; t += 4) {
        const float* row = nin + (size_t)(base + t) * 256;
        float acc = 0.f;
#pragma unroll
        for (int i = 0; i < 8; i++) acc += row[lane + 32 * i] * s_w[lane + 32 * i];
        acc = warpsum(acc);
        if (!lane) s_attn[t] = acc * 0.08838834764831845f;
    }
    __syncthreads();
    if (tid == 0) {
        float m = -1e30f;
        for (int t = 0; t < cnt; t++) m = fmaxf(m, s_attn[t]);
        float s = 0.f;
        for (int t = 0; t < cnt; t++) { float e = expf(s_attn[t] - m); s_attn[t] = e; s += e; }
        float inv = 1.f / (s + 1e-16f);
        for (int t = 0; t < cnt; t++) s_attn[t] *= inv;
    }
    __syncthreads();
    float acc0 = 0.f, acc1 = 0.f, sum0 = 0.f, sum1 = 0.f;
    for (int t = 0; t < cnt; t++) {
        size_t ro = (size_t)(base + t) * 256;
        const float* row = nin + ro;
        float v0 = row[tid], v1 = row[tid + 128];
        float a = s_attn[t];
        acc0 += a * v0; acc1 += a * v1;
        sum0 += v0;     sum1 += v1;
        // fused bf16 split of n for the gate HMMA GEMM
        __nv_bfloat16 nh0 = __float2bfloat16(v0);
        __nv_bfloat16 nh1 = __float2bfloat16(v1);
        g_nh[ro + tid] = nh0;           g_nh[ro + tid + 128] = nh1;
        g_nl[ro + tid] = __float2bfloat16(v0 - __bfloat162float(nh0));
        g_nl[ro + tid + 128] = __float2bfloat16(v1 - __bfloat162float(nh1));
    }
    float gate0 = tanhf(acc0), gate1 = tanhf(acc1);
    size_t o = (size_t)g * 256 + tid;
    float c0 = cin[o], c1 = cin[o + 128];
    out_gate[o] = gate0;            out_gate[o + 128] = gate1;
    float ca0 = c0 * gate0, ca1 = c1 * gate1;
    __nv_bfloat16 h0 = __float2bfloat16(ca0);
    __nv_bfloat16 h1 = __float2bfloat16(ca1);
    g_cadjh[o] = h0;                g_cadjh[o + 128] = h1;
    g_cadjl[o] = __float2bfloat16(ca0 - __bfloat162float(h0));
    g_cadjl[o + 128] = __float2bfloat16(ca1 - __bfloat162float(h1));
    out_nein[o] = c0 + sum0;        out_nein[o + 128] = c1 + sum1;
}

// ---------------- neighb_expr from bf16 splits --------------------------------
__global__ void __launch_bounds__(128) segmean_nadj(
    const float* __restrict__ counts_f, const int* __restrict__ offs,
    float* __restrict__ out_ne) {
    int g = blockIdx.x;
    int tid = threadIdx.x;
    int base = offs[g];
    int cnt = (int)(counts_f[g] + 0.5f);
    float inv = 1.f / counts_f[g];
    float s0 = 0.f, s1 = 0.f;
    for (int t = 0; t < cnt; t++) {
        size_t ro = (size_t)(base + t) * 256;
        s0 += __bfloat162float(g_nadjh[ro + tid]) + __bfloat162float(g_nadjl[ro + tid]);
        s1 += __bfloat162float(g_nadjh[ro + tid + 128]) + __bfloat162float(g_nadjl[ro + tid + 128]);
    }
    out_ne[(size_t)g * 256 + tid] = s0 * inv;
    out_ne[(size_t)g * 256 + 128 + tid] = s1 * inv;
}

// ---------------- per-node scalars (neighbors) --------------------------------
__global__ void node_scalars_n(const float* __restrict__ a_src1,
                               const float* __restrict__ a_feat, int T) {
    int row = blockIdx.x * 4 + (threadIdx.x >> 5);
    if (row >= T) return;
    int lane = threadIdx.x & 31;
    const float* h = g_hn + (size_t)row * 128;
    float v[4];
#pragma unroll
    for (int i = 0; i < 4; i++) v[i] = h[lane + 32 * i];
#pragma unroll
    for (int i = 0; i < 4; i++) {
        float s = warpsum(v[i] * a_src1[i * 32 + lane]);
        if (!lane) g_s1n[(size_t)row * 4 + i] = s;
    }
    float fs = 0.f, fd = 0.f;
#pragma unroll
    for (int i = 0; i < 4; i++) {
        fs += v[i] * a_feat[i * 32 + lane];
        fd += v[i] * a_feat[128 + i * 32 + lane];
    }
    fs = warpsum(fs); fd = warpsum(fd);
    if (!lane) { g_fsn[row] = fs; g_fdn[row] = fd; }
}

// ---------------- per-node scalars (centers) ----------------------------------
__global__ void node_scalars_c(const float* __restrict__ a_dst1,
                               const float* __restrict__ a_feat) {
    int row = blockIdx.x * 4 + (threadIdx.x >> 5);
    if (row >= BB) return;
    int lane = threadIdx.x & 31;
    const float* h = g_hc + (size_t)row * 128;
    float v[4];
#pragma unroll
    for (int i = 0; i < 4; i++) v[i] = h[lane + 32 * i];
#pragma unroll
    for (int i = 0; i < 4; i++) {
        float d = warpsum(v[i] * a_dst1[i * 32 + lane]);
        if (!lane) g_d1c[row * 4 + i] = d;
    }
    float fs = 0.f, fd = 0.f;
#pragma unroll
    for (int i = 0; i < 4; i++) {
        fs += v[i] * a_feat[i * 32 + lane];
        fd += v[i] * a_feat[128 + i * 32 + lane];
    }
    fs = warpsum(fs); fd = warpsum(fd);
    if (!lane) { g_fsc[row] = fs; g_fdc[row] = fd; }
}

// ---------------- GAT1 ---------------------------------------------------------
__global__ void __launch_bounds__(128) gat1(
    const float* __restrict__ counts_f, const int* __restrict__ offs,
    const int* __restrict__ edges, int T, float* __restrict__ out_ew) {
    int g = blockIdx.x;
    int tid = threadIdx.x, lane = tid & 31, warp = tid >> 5;
    int base = offs[g];
    int cnt = (int)(counts_f[g] + 0.5f);
    int E2 = 2 * T;
    __shared__ float s_alpha[32][4];
    int head = warp;
    float d1 = g_d1c[g * 4 + head];
    float m = -1e30f;
    for (int t = lane; t < cnt; t += 32) {
        float e = lrelu02(g_s1n[(size_t)(base + t) * 4 + head] + d1);
        s_alpha[t][head] = e;
        m = fmaxf(m, e);
    }
    m = warpmax(m);
    float ssum = 0.f;
    for (int t = lane; t < cnt; t += 32) {
        float ex = expf(s_alpha[t][head] - m);
        s_alpha[t][head] = ex;
        ssum += ex;
    }
    ssum = warpsum(ssum);
    float inv = 1.f / (ssum + 1e-16f);
    for (int t = lane; t < cnt; t += 32) s_alpha[t][head] *= inv;
    __syncthreads();
    int h4 = tid >> 5;
    float acc = 0.f;
    for (int t = 0; t < cnt; t++)
        acc += s_alpha[t][h4] * g_hn[(size_t)(base + t) * 128 + tid];
    size_t xo = (size_t)g * 128 + tid;
    g_xc[xo] = acc;
    __nv_bfloat16 xh = __float2bfloat16(acc);
    g_xch[xo] = xh;
    g_xcl[xo] = __float2bfloat16(acc - __bfloat162float(xh));
    if (tid < cnt) {
        int t = tid;
        int ei = base + t;
        float am = 0.25f * (s_alpha[t][0] + s_alpha[t][1] + s_alpha[t][2] + s_alpha[t][3]);
        float a2 = sigm(g_fsn[ei] + g_fdc[g]);
        float4 r1 = make_float4((float)edges[ei], (float)edges[E2 + ei], am, a2);
        *(float4*)(out_ew + (size_t)ei * 4) = r1;
        int ej = T + ei;
        float a2b = sigm(g_fsc[g] + g_fdn[ei]);
        float4 r2 = make_float4((float)edges[ej], (float)edges[E2 + ej], 1.0f, a2b);
        *(float4*)(out_ew + (size_t)ej * 4) = r2;
    }
}

// ---------------- h2 scalars ----------------------------------------------------
__global__ void h2_scalars(const float* __restrict__ a_src2,
                           const float* __restrict__ a_dst2) {
    int row = blockIdx.x * 4 + (threadIdx.x >> 5);
    if (row >= BB) return;
    int lane = threadIdx.x & 31;
    const float* h = g_h2 + (size_t)row * 128;
    float s = 0.f, d = 0.f;
#pragma unroll
    for (int i = 0; i < 4; i++) {
        float v = h[lane + 32 * i];
        s += v * a_src2[lane + 32 * i];
        d += v * a_dst2[lane + 32 * i];
    }
    s = warpsum(s); d = warpsum(d);
    if (!lane) { g_s2[row] = s; g_d2[row] = d; }
}

// ---------------- VT graph softmax ----------------------------------------------
__global__ void vt_pass1(const int* __restrict__ evt) {
    int i = blockIdx.x * blockDim.x + threadIdx.x;
    if (i >= EVT) return;
    int sv = evt[i], dv = evt[EVT + i];
    float e = lrelu02(g_s2[sv] + g_d2[dv]);
    g_e2v[i] = e;
    atomicMaxFloat(&g_vmax[dv], e);
}
__global__ void vt_pass2(const int* __restrict__ evt) {
    int i = blockIdx.x * blockDim.x + threadIdx.x;
    if (i >= EVT) return;
    int dv = evt[EVT + i];
    float ex = expf(g_e2v[i] - g_vmax[dv]);
    g_e2v[i] = ex;
    atomicAdd(&g_vsum[dv], ex);
}
__global__ void __launch_bounds__(128) vt_pass3(const int* __restrict__ evt,
                                                float* __restrict__ out_alpha,
                                                float* __restrict__ out_xn) {
    int i = blockIdx.x;
    int sv = evt[i], dv = evt[EVT + i];
    float alpha = g_e2v[i] / (g_vsum[dv] + 1e-16f);
    if (threadIdx.x == 0) out_alpha[i] = alpha;
    atomicAdd(&out_xn[(size_t)dv * 128 + threadIdx.x],
              alpha * g_h2[(size_t)sv * 128 + threadIdx.x]);
}

// ---------------- host launcher --------------------------------------------------
extern "C" void kernel_launch(void* const* d_in, const int* in_sizes, int n_in,
                              void* d_out, int out_size) {
    const float* c_in    = (const float*)d_in[0];
    const float* nb_in   = (const float*)d_in[1];
    const float* counts  = (const float*)d_in[2];
    const float* Wq_c    = (const float*)d_in[3];
    const float* Wk_c    = (const float*)d_in[4];
    const float* Wq_n    = (const float*)d_in[5];
    const float* Wk_n    = (const float*)d_in[6];
    const float* W1      = (const float*)d_in[7];
    const float* a_src1  = (const float*)d_in[8];
    const float* a_dst1  = (const float*)d_in[9];
    const float* a_feat  = (const float*)d_in[10];
    const float* W2      = (const float*)d_in[11];
    const float* a_src2  = (const float*)d_in[12];
    const float* a_dst2  = (const float*)d_in[13];
    const int*   seg     = (const int*)d_in[14];
    const int*   offs    = (const int*)d_in[17];
    const int*   edges   = (const int*)d_in[18];
    const int*   evt     = (const int*)d_in[19];
    int T = in_sizes[1] / GG;

    float* out = (float*)d_out;
    float* out_xn   = out;
    float* out_gate = out_xn + (size_t)BB * EMBD;
    float* out_attn = out_gate + (size_t)BB * GG;
    float* out_ne   = out_attn + (size_t)BB * GG;
    float* out_nein = out_ne + (size_t)BB * GG;
    float* out_ew   = out_nein + (size_t)BB * GG;
    float* out_avt  = out_ew + (size_t)8 * T;

    float *p_w, *p_ck, *p_hn, *p_hc, *p_h2;
    __nv_bfloat16 *p_ch, *p_cl;
    cudaGetSymbolAddress((void**)&p_w, g_w);
    cudaGetSymbolAddress((void**)&p_ck, g_ck);
    cudaGetSymbolAddress((void**)&p_hn, g_hn);
    cudaGetSymbolAddress((void**)&p_hc, g_hc);
    cudaGetSymbolAddress((void**)&p_h2, g_h2);
    cudaGetSymbolAddress((void**)&p_ch, g_ch);
    cudaGetSymbolAddress((void**)&p_cl, g_cl);

    int tilesT = (T + 127) / 128;

    init_kernel<<<(BB * EMBD + 255) / 256, 256>>>(out_xn);
    compute_M1<<<GG, 256>>>(Wq_c, Wk_c);
    prep_B_gate<<<256, 256>>>(Wq_n);
    prep_B_w1<<<128, 256>>>(W1);
    prep_B_w2<<<64, 256>>>(W2);
    prep_B_M1Wk<<<256, 256>>>(Wk_n);
    conv_split<<<(BB * 64 + 255) / 256, 256>>>((const float4*)c_in, p_ch, p_cl, BB * 64);

    // w = c @ M1  AND  ck = c @ Wk_n via HMMA
    hmma_wck<<<dim3(2, BB / 128, 2), 128>>>(p_w, p_ck);

    stageA<<<BB, 128>>>(c_in, nb_in, counts, offs, out_gate, out_nein);

    // n_adj (bf16 splits) via HMMA + fused tanh gate epilogue
    hmma_gate<<<dim3(2, tilesT), 128>>>(nb_in, p_ck, seg, offs, out_attn, T);
    segmean_nadj<<<BB, 128>>>(counts, offs, out_ne);

    // h = [nadj; cadj] @ W1 via HMMA
    hmma_w1<<<dim3(1, tilesT + BB / 128), 128>>>(p_hn, p_hc, T, BB, tilesT);

    node_scalars_n<<<(T + 3) / 4, 128>>>(a_src1, a_feat, T);
    node_scalars_c<<<BB / 4, 128>>>(a_dst1, a_feat);

    gat1<<<BB, 128>>>(counts, offs, edges, T, out_ew);

    // h2 = xc @ W2 via HMMA
    hmma_h2<<<dim3(1, BB / 128), 128>>>(p_h2);
    h2_scalars<<<BB / 4, 128>>>(a_src2, a_dst2);

    vt_pass1<<<(EVT + 255) / 256, 256>>>(evt);
    vt_pass2<<<(EVT + 255) / 256, 256>>>(evt);
    vt_pass3<<<EVT, 128>>>(evt, out_avt, out_xn);
}

// round 7
// speedup vs baseline: 1.5700x; 1.0964x over previous
#include <cuda_runtime.h>
#include <cuda_bf16.h>
#include <math.h>
#include <stdint.h>

#define BB 8192
#define GG 256
#define EMBD 128
#define NHEAD 4
#define EVT 65536
#define TMAXN 196608  /* 8192 * 24 (counts in [8,24]) */

// ---------------- scratch (static device globals) ----------------------------
__device__ float g_w[BB * GG];
__device__ float g_ck[BB * GG];
__device__ float g_hn[(size_t)TMAXN * EMBD];
__device__ float g_hc[BB * EMBD];
__device__ float g_xc[BB * EMBD];
__device__ float g_h2[BB * EMBD];
__device__ float g_s1n[(size_t)TMAXN * NHEAD];
__device__ float g_d1c[BB * NHEAD];
__device__ float g_fsn[TMAXN];
__device__ float g_fdn[TMAXN];
__device__ float g_fsc[BB];
__device__ float g_fdc[BB];
__device__ float g_s2[BB];
__device__ float g_d2[BB];
__device__ float g_e2v[EVT];
__device__ float g_vmax[BB];
__device__ float g_vsum[BB];
// bf16 split operands
__device__ __nv_bfloat16 g_nh[(size_t)TMAXN * GG];
__device__ __nv_bfloat16 g_nl[(size_t)TMAXN * GG];
__device__ __nv_bfloat16 g_nadjh[(size_t)TMAXN * GG];
__device__ __nv_bfloat16 g_nadjl[(size_t)TMAXN * GG];
__device__ __nv_bfloat16 g_cadjh[BB * GG];
__device__ __nv_bfloat16 g_cadjl[BB * GG];
__device__ __nv_bfloat16 g_ch[BB * GG];
__device__ __nv_bfloat16 g_cl[BB * GG];
__device__ __nv_bfloat16 g_xch[BB * EMBD];
__device__ __nv_bfloat16 g_xcl[BB * EMBD];
__device__ __nv_bfloat16 g_Bqh[GG * GG];    // Wq_n^T  [n][k]
__device__ __nv_bfloat16 g_Bql[GG * GG];
__device__ __nv_bfloat16 g_B1h[EMBD * GG];  // W1^T    [n][k]
__device__ __nv_bfloat16 g_B1l[EMBD * GG];
__device__ __nv_bfloat16 g_BM1h[GG * GG];   // M1^T    [n][k]
__device__ __nv_bfloat16 g_BM1l[GG * GG];
__device__ __nv_bfloat16 g_BWkh[GG * GG];   // Wk_n^T  [n][k]
__device__ __nv_bfloat16 g_BWkl[GG * GG];
__device__ __nv_bfloat16 g_B2h[EMBD * EMBD];// W2^T    [n][k]
__device__ __nv_bfloat16 g_B2l[EMBD * EMBD];

// ---------------- helpers ----------------------------------------------------
__device__ __forceinline__ float warpsum(float v) {
#pragma unroll
    for (int o = 16; o; o >>= 1) v += __shfl_xor_sync(0xffffffffu, v, o);
    return v;
}
__device__ __forceinline__ float warpmax(float v) {
#pragma unroll
    for (int o = 16; o; o >>= 1) v = fmaxf(v, __shfl_xor_sync(0xffffffffu, v, o));
    return v;
}
__device__ __forceinline__ void atomicMaxFloat(float* addr, float value) {
    if (value >= 0.f) atomicMax((int*)addr, __float_as_int(value));
    else              atomicMin((unsigned int*)addr, __float_as_uint(value));
}
__device__ __forceinline__ float lrelu02(float x) { return x > 0.f ? x : 0.2f * x; }
__device__ __forceinline__ float sigm(float x) { return 1.f / (1.f + expf(-x)); }

__device__ __forceinline__ uint32_t smem_u32(const void* p) {
    uint32_t a;
    asm("{ .reg .u64 t; cvta.to.shared.u64 t, %1; cvt.u32.u64 %0, t; }"
        : "=r"(a) : "l"(p));
    return a;
}
__device__ __forceinline__ void bsplit2(float x, float y, uint32_t& h, uint32_t& l) {
    unsigned short hx = __bfloat16_as_ushort(__float2bfloat16(x));
    unsigned short hy = __bfloat16_as_ushort(__float2bfloat16(y));
    float rx = x - __bfloat162float(__ushort_as_bfloat16(hx));
    float ry = y - __bfloat162float(__ushort_as_bfloat16(hy));
    unsigned short lx = __bfloat16_as_ushort(__float2bfloat16(rx));
    unsigned short ly = __bfloat16_as_ushort(__float2bfloat16(ry));
    h = (uint32_t)hx | ((uint32_t)hy << 16);
    l = (uint32_t)lx | ((uint32_t)ly << 16);
}

// ---------------- HMMA primitives --------------------------------------------
__device__ __forceinline__ void ldsm_x4(uint32_t addr, uint32_t& r0, uint32_t& r1,
                                        uint32_t& r2, uint32_t& r3) {
    asm volatile("ldmatrix.sync.aligned.m8n8.x4.shared.b16 {%0,%1,%2,%3}, [%4];"
                 : "=r"(r0), "=r"(r1), "=r"(r2), "=r"(r3) : "r"(addr));
}
__device__ __forceinline__ void mma_bf16(float* c, const uint32_t* a,
                                         uint32_t b0, uint32_t b1) {
    asm volatile(
        "mma.sync.aligned.m16n8k16.row.col.f32.bf16.bf16.f32 "
        "{%0,%1,%2,%3}, {%4,%5,%6,%7}, {%8,%9}, {%0,%1,%2,%3};"
        : "+f"(c[0]), "+f"(c[1]), "+f"(c[2]), "+f"(c[3])
        : "r"(a[0]), "r"(a[1]), "r"(a[2]), "r"(a[3]), "r"(b0), "r"(b1));
}

// stage 128 rows x 16 bf16 (32B) starting at column k0; 48B smem row stride.
__device__ __forceinline__ void stage_tile(const __nv_bfloat16* __restrict__ src,
                                           int row0, int M, int k0, int rowElems,
                                           __nv_bfloat16* dst, int tid) {
#pragma unroll
    for (int s = 0; s < 2; s++) {
        int idx = tid + s * 128;
        int row = idx >> 1, half = idx & 1;
        int4 v = make_int4(0, 0, 0, 0);
        if (row0 + row < M)
            v = *(const int4*)((const uint8_t*)src +
                               (size_t)(row0 + row) * (rowElems * 2) +
                               (size_t)(k0 * 2 + half * 16));
        *(int4*)((uint8_t*)dst + row * 48 + half * 16) = v;
    }
}

// all-operands-once mainloop: per k-step stage Ah,Al,Bh,Bl and issue
// the 3 split-products (Ah*Bh + Ah*Bl + Al*Bh) from registers.
#define HMMA_MAINLOOP2(AH_, AL_, BH_, BL_, M_, row0_, col0_, KELA_, KELB_, KSTEPS_) \
    {                                                                          \
        const int lane_ = tid & 31, w_ = tid >> 5;                             \
        const int wr_ = w_ >> 1, wc_ = w_ & 1;                                 \
        const uint32_t aoff_ =                                                 \
            (uint32_t)((wr_ * 64 + (lane_ & 15)) * 48 + (lane_ >> 4) * 16);    \
        const uint32_t boff_ =                                                 \
            (uint32_t)((wc_ * 64 + (lane_ & 15)) * 48 + (lane_ >> 4) * 16);    \
        int buf = 0;                                                           \
        stage_tile(AH_, row0_, M_, 0, KELA_, &sA[0][0][0], tid);               \
        stage_tile(AL_, row0_, M_, 0, KELA_, &sA[0][1][0], tid);               \
        stage_tile(BH_, col0_, 1 << 30, 0, KELB_, &sB[0][0][0], tid);          \
        stage_tile(BL_, col0_, 1 << 30, 0, KELB_, &sB[0][1][0], tid);          \
        __syncthreads();                                                       \
        for (int it = 0; it < (KSTEPS_); it++) {                               \
            if (it + 1 < (KSTEPS_)) {                                          \
                int k0 = (it + 1) * 16;                                        \
                stage_tile(AH_, row0_, M_, k0, KELA_, &sA[buf ^ 1][0][0], tid);\
                stage_tile(AL_, row0_, M_, k0, KELA_, &sA[buf ^ 1][1][0], tid);\
                stage_tile(BH_, col0_, 1 << 30, k0, KELB_, &sB[buf ^ 1][0][0], tid); \
                stage_tile(BL_, col0_, 1 << 30, k0, KELB_, &sB[buf ^ 1][1][0], tid); \
            }                                                                  \
            uint32_t aB0 = smem_u32(&sA[buf][0][0]) + aoff_;                   \
            uint32_t aB1 = smem_u32(&sA[buf][1][0]) + aoff_;                   \
            uint32_t bB0 = smem_u32(&sB[buf][0][0]) + boff_;                   \
            uint32_t bB1 = smem_u32(&sB[buf][1][0]) + boff_;                   \
            uint32_t aH[4][4], aL[4][4], bH[4][4], bL[4][4];                   \
            _Pragma("unroll")                                                  \
            for (int rt = 0; rt < 4; rt++) {                                   \
                ldsm_x4(aB0 + rt * 768, aH[rt][0], aH[rt][1], aH[rt][2], aH[rt][3]); \
                ldsm_x4(aB1 + rt * 768, aL[rt][0], aL[rt][1], aL[rt][2], aL[rt][3]); \
            }                                                                  \
            _Pragma("unroll")                                                  \
            for (int cp = 0; cp < 4; cp++) {                                   \
                ldsm_x4(bB0 + cp * 768, bH[cp][0], bH[cp][1], bH[cp][2], bH[cp][3]); \
                ldsm_x4(bB1 + cp * 768, bL[cp][0], bL[cp][1], bL[cp][2], bL[cp][3]); \
            }                                                                  \
            _Pragma("unroll")                                                  \
            for (int rt = 0; rt < 4; rt++)                                     \
                _Pragma("unroll")                                              \
                for (int cp = 0; cp < 4; cp++) {                               \
                    mma_bf16(acc[rt][2 * cp],     aH[rt], bH[cp][0], bH[cp][2]); \
                    mma_bf16(acc[rt][2 * cp + 1], aH[rt], bH[cp][1], bH[cp][3]); \
                    mma_bf16(acc[rt][2 * cp],     aH[rt], bL[cp][0], bL[cp][2]); \
                    mma_bf16(acc[rt][2 * cp + 1], aH[rt], bL[cp][1], bL[cp][3]); \
                    mma_bf16(acc[rt][2 * cp],     aL[rt], bH[cp][0], bH[cp][2]); \
                    mma_bf16(acc[rt][2 * cp + 1], aL[rt], bH[cp][1], bH[cp][3]); \
                }                                                              \
            __syncthreads();                                                   \
            buf ^= 1;                                                          \
        }                                                                      \
    }

#define SMEM_DECL                                                              \
    __shared__ __align__(16) __nv_bfloat16 sA[2][2][128 * 24];                 \
    __shared__ __align__(16) __nv_bfloat16 sB[2][2][128 * 24];

// ---------------- merged prep kernel ------------------------------------------
__global__ void prep_misc(const float* __restrict__ Wq_n,
                          const float* __restrict__ W1,
                          const float* __restrict__ W2,
                          const float* __restrict__ Wk_n,
                          const float4* __restrict__ cin) {
    int b = blockIdx.x, tid = threadIdx.x;
    if (b < 256) {                       // Wq_n -> Bqh/Bql transposed
        int idx = b * 256 + tid, k = idx >> 8, n = idx & 255;
        float x = Wq_n[k * 256 + n];
        __nv_bfloat16 h = __float2bfloat16(x);
        g_Bqh[n * 256 + k] = h;
        g_Bql[n * 256 + k] = __float2bfloat16(x - __bfloat162float(h));
    } else if (b < 384) {                // W1
        int idx = (b - 256) * 256 + tid, k = idx >> 7, n = idx & 127;
        float x = W1[k * 128 + n];
        __nv_bfloat16 h = __float2bfloat16(x);
        g_B1h[n * 256 + k] = h;
        g_B1l[n * 256 + k] = __float2bfloat16(x - __bfloat162float(h));
    } else if (b < 448) {                // W2
        int idx = (b - 384) * 256 + tid, k = idx >> 7, n = idx & 127;
        float x = W2[k * 128 + n];
        __nv_bfloat16 h = __float2bfloat16(x);
        g_B2h[n * 128 + k] = h;
        g_B2l[n * 128 + k] = __float2bfloat16(x - __bfloat162float(h));
    } else if (b < 704) {                // Wk_n
        int idx = (b - 448) * 256 + tid, k = idx >> 8, n = idx & 255;
        float x = Wk_n[k * 256 + n];
        __nv_bfloat16 h = __float2bfloat16(x);
        g_BWkh[n * 256 + k] = h;
        g_BWkl[n * 256 + k] = __float2bfloat16(x - __bfloat162float(h));
    } else {                             // conv_split of c_in (BB*64 float4)
        int i = (b - 704) * 256 + tid;
        float4 v = cin[i];
        uint32_t h0, l0, h1, l1;
        bsplit2(v.x, v.y, h0, l0);
        bsplit2(v.z, v.w, h1, l1);
        ((uint32_t*)g_ch)[i * 2] = h0; ((uint32_t*)g_ch)[i * 2 + 1] = h1;
        ((uint32_t*)g_cl)[i * 2] = l0; ((uint32_t*)g_cl)[i * 2 + 1] = l1;
    }
}

// ---------------- M1 = Wq_c @ Wk_c^T, fused transposed split ------------------
__global__ void compute_M1(const float* __restrict__ Wq_c,
                           const float* __restrict__ Wk_c) {
    int p = blockIdx.x;
    int tid = threadIdx.x, lane = tid & 31, warp = tid >> 5;
    __shared__ float sq[128];
    if (tid < 128) sq[tid] = Wq_c[p * 128 + tid];
    __syncthreads();
    for (int k = warp; k < 256; k += 8) {
        const float* row = Wk_c + (size_t)k * 128;
        float acc = 0.f;
#pragma unroll
        for (int i = 0; i < 4; i++) acc += row[lane + 32 * i] * sq[lane + 32 * i];
        acc = warpsum(acc);
        if (!lane) {
            // M1[p][k]; B^T layout [n][kk] with (n,kk) = (k, p)
            __nv_bfloat16 h = __float2bfloat16(acc);
            g_BM1h[k * 256 + p] = h;
            g_BM1l[k * 256 + p] = __float2bfloat16(acc - __bfloat162float(h));
        }
    }
}

// ================= HMMA GEMM: w/ck dual-B =====================================
__global__ void __launch_bounds__(128) hmma_wck(float* __restrict__ Cw,
                                                float* __restrict__ Cck) {
    SMEM_DECL
    const int tid = threadIdx.x;
    const int row0 = blockIdx.y * 128, col0 = blockIdx.x * 128;
    const __nv_bfloat16* Bh = blockIdx.z ? g_BWkh : g_BM1h;
    const __nv_bfloat16* Bl = blockIdx.z ? g_BWkl : g_BM1l;
    float* C = blockIdx.z ? Cck : Cw;
    float acc[4][8][4] = {};
    HMMA_MAINLOOP2(g_ch, g_cl, Bh, Bl, BB, row0, col0, 256, 256, 16);
    const int lane = tid & 31, w = tid >> 5, wr = w >> 1, wc = w & 1;
    const int g = lane >> 2, q = lane & 3;
#pragma unroll
    for (int rt = 0; rt < 4; rt++)
#pragma unroll
        for (int i = 0; i < 2; i++) {
            int er = row0 + wr * 64 + rt * 16 + g + i * 8;
            float* crow = C + (size_t)er * 256;
#pragma unroll
            for (int ct = 0; ct < 8; ct++) {
                int c = col0 + wc * 64 + ct * 8 + q * 2;
                *(float2*)(crow + c) = make_float2(acc[rt][ct][i * 2 + 0],
                                                   acc[rt][ct][i * 2 + 1]);
            }
        }
}

// ================= HMMA GEMM: gate ============================================
__global__ void __launch_bounds__(128) hmma_gate(
    const float* __restrict__ Afp, const float* __restrict__ ck,
    const int* __restrict__ seg, const int* __restrict__ offs,
    float* __restrict__ out_attn, int M) {
    SMEM_DECL
    const int tid = threadIdx.x;
    const int row0 = blockIdx.y * 128, col0 = blockIdx.x * 128;
    float acc[4][8][4] = {};
    HMMA_MAINLOOP2(g_nh, g_nl, g_Bqh, g_Bql, M, row0, col0, 256, 256, 16);
    const int lane = tid & 31, w = tid >> 5, wr = w >> 1, wc = w & 1;
    const int g = lane >> 2, q = lane & 3;
#pragma unroll
    for (int rt = 0; rt < 4; rt++)
#pragma unroll
        for (int i = 0; i < 2; i++) {
            int er = row0 + wr * 64 + rt * 16 + g + i * 8;
            if (er >= M) continue;
            int sg = seg[er];
            bool first = (offs[sg] == er);
            const float* ckrow = ck + (size_t)sg * 256;
            const float* arow = Afp + (size_t)er * 256;
#pragma unroll
            for (int ct = 0; ct < 8; ct++) {
                int c = col0 + wc * 64 + ct * 8 + q * 2;
                float2 ckv = *(const float2*)(ckrow + c);
                float2 av = *(const float2*)(arow + c);
                float g0 = tanhf(acc[rt][ct][i * 2 + 0] * ckv.x);
                float g1 = tanhf(acc[rt][ct][i * 2 + 1] * ckv.y);
                uint32_t hh, ll;
                bsplit2(av.x * g0, av.y * g1, hh, ll);
                *(uint32_t*)((uint8_t*)g_nadjh + (size_t)er * 512 + c * 2) = hh;
                *(uint32_t*)((uint8_t*)g_nadjl + (size_t)er * 512 + c * 2) = ll;
                if (first)
                    *(float2*)(out_attn + (size_t)sg * 256 + c) = make_float2(g0, g1);
            }
        }
}

// ================= HMMA GEMM: [nadj; cadj] @ W1 ===============================
__global__ void __launch_bounds__(128) hmma_w1(
    float* __restrict__ C0, float* __restrict__ C1,
    int M0, int M1, int tiles0) {
    SMEM_DECL
    const int tid = threadIdx.x;
    int t = blockIdx.y;
    const __nv_bfloat16 *Ah, *Al;
    float* C; int M, row0;
    if (t < tiles0) { Ah = g_nadjh; Al = g_nadjl; C = C0; M = M0; row0 = t * 128; }
    else            { Ah = g_cadjh; Al = g_cadjl; C = C1; M = M1; row0 = (t - tiles0) * 128; }
    float acc[4][8][4] = {};
    HMMA_MAINLOOP2(Ah, Al, g_B1h, g_B1l, M, row0, 0, 256, 256, 16);
    const int lane = tid & 31, w = tid >> 5, wr = w >> 1, wc = w & 1;
    const int g = lane >> 2, q = lane & 3;
#pragma unroll
    for (int rt = 0; rt < 4; rt++)
#pragma unroll
        for (int i = 0; i < 2; i++) {
            int er = row0 + wr * 64 + rt * 16 + g + i * 8;
            if (er >= M) continue;
            float* crow = C + (size_t)er * 128;
#pragma unroll
            for (int ct = 0; ct < 8; ct++) {
                int c = wc * 64 + ct * 8 + q * 2;
                *(float2*)(crow + c) = make_float2(acc[rt][ct][i * 2 + 0],
                                                   acc[rt][ct][i * 2 + 1]);
            }
        }
}

// ================= HMMA GEMM: h2 = xc @ W2  (K=128, N=128) ====================
__global__ void __launch_bounds__(128) hmma_h2(float* __restrict__ C) {
    SMEM_DECL
    const int tid = threadIdx.x;
    const int row0 = blockIdx.y * 128;
    float acc[4][8][4] = {};
    HMMA_MAINLOOP2(g_xch, g_xcl, g_B2h, g_B2l, BB, row0, 0, 128, 128, 8);
    const int lane = tid & 31, w = tid >> 5, wr = w >> 1, wc = w & 1;
    const int g = lane >> 2, q = lane & 3;
#pragma unroll
    for (int rt = 0; rt < 4; rt++)
#pragma unroll
        for (int i = 0; i < 2; i++) {
            int er = row0 + wr * 64 + rt * 16 + g + i * 8;
            float* crow = C + (size_t)er * 128;
#pragma unroll
            for (int ct = 0; ct < 8; ct++) {
                int c = wc * 64 + ct * 8 + q * 2;
                *(float2*)(crow + c) = make_float2(acc[rt][ct][i * 2 + 0],
                                                   acc[rt][ct][i * 2 + 1]);
            }
        }
}

// ---------------- init --------------------------------------------------------
__global__ void init_kernel(float* __restrict__ out_xn) {
    int i = blockIdx.x * blockDim.x + threadIdx.x;
    if (i < BB * EMBD) out_xn[i] = 0.f;
    if (i < BB) { g_vmax[i] = -1e30f; g_vsum[i] = 0.f; }
}

// ---------------- stage A: cross-attention + n/cadj splits --------------------
__global__ void __launch_bounds__(128) stageA(
    const float* __restrict__ cin, const float* __restrict__ nin,
    const float* __restrict__ counts_f, const int* __restrict__ offs,
    float* __restrict__ out_gate, float* __restrict__ out_nein) {
    int g = blockIdx.x;
    int tid = threadIdx.x, lane = tid & 31, warp = tid >> 5;
    int base = offs[g];
    int cnt = (int)(counts_f[g] + 0.5f);
    __shared__ float s_w[256];
    __shared__ float s_attn[32];
    s_w[tid] = g_w[(size_t)g * 256 + tid];
    s_w[tid + 128] = g_w[(size_t)g * 256 + 128 + tid];
    __syncthreads();
    for (int t = warp; t < cnt; t += 4) {
        const float* row = nin + (size_t)(base + t) * 256;
        float acc = 0.f;
#pragma unroll
        for (int i = 0; i < 8; i++) acc += row[lane + 32 * i] * s_w[lane + 32 * i];
        acc = warpsum(acc);
        if (!lane) s_attn[t] = acc * 0.08838834764831845f;
    }
    __syncthreads();
    if (tid == 0) {
        float m = -1e30f;
        for (int t = 0; t < cnt; t++) m = fmaxf(m, s_attn[t]);
        float s = 0.f;
        for (int t = 0; t < cnt; t++) { float e = expf(s_attn[t] - m); s_attn[t] = e; s += e; }
        float inv = 1.f / (s + 1e-16f);
        for (int t = 0; t < cnt; t++) s_attn[t] *= inv;
    }
    __syncthreads();
    float acc0 = 0.f, acc1 = 0.f, sum0 = 0.f, sum1 = 0.f;
    for (int t = 0; t < cnt; t++) {
        size_t ro = (size_t)(base + t) * 256;
        const float* row = nin + ro;
        float v0 = row[tid], v1 = row[tid + 128];
        float a = s_attn[t];
        acc0 += a * v0; acc1 += a * v1;
        sum0 += v0;     sum1 += v1;
        __nv_bfloat16 nh0 = __float2bfloat16(v0);
        __nv_bfloat16 nh1 = __float2bfloat16(v1);
        g_nh[ro + tid] = nh0;           g_nh[ro + tid + 128] = nh1;
        g_nl[ro + tid] = __float2bfloat16(v0 - __bfloat162float(nh0));
        g_nl[ro + tid + 128] = __float2bfloat16(v1 - __bfloat162float(nh1));
    }
    float gate0 = tanhf(acc0), gate1 = tanhf(acc1);
    size_t o = (size_t)g * 256 + tid;
    float c0 = cin[o], c1 = cin[o + 128];
    out_gate[o] = gate0;            out_gate[o + 128] = gate1;
    float ca0 = c0 * gate0, ca1 = c1 * gate1;
    __nv_bfloat16 h0 = __float2bfloat16(ca0);
    __nv_bfloat16 h1 = __float2bfloat16(ca1);
    g_cadjh[o] = h0;                g_cadjh[o + 128] = h1;
    g_cadjl[o] = __float2bfloat16(ca0 - __bfloat162float(h0));
    g_cadjl[o + 128] = __float2bfloat16(ca1 - __bfloat162float(h1));
    out_nein[o] = c0 + sum0;        out_nein[o + 128] = c1 + sum1;
}

// ---------------- neighb_expr from bf16 splits --------------------------------
__global__ void __launch_bounds__(128) segmean_nadj(
    const float* __restrict__ counts_f, const int* __restrict__ offs,
    float* __restrict__ out_ne) {
    int g = blockIdx.x;
    int tid = threadIdx.x;
    int base = offs[g];
    int cnt = (int)(counts_f[g] + 0.5f);
    float inv = 1.f / counts_f[g];
    float s0 = 0.f, s1 = 0.f;
    for (int t = 0; t < cnt; t++) {
        size_t ro = (size_t)(base + t) * 256;
        s0 += __bfloat162float(g_nadjh[ro + tid]) + __bfloat162float(g_nadjl[ro + tid]);
        s1 += __bfloat162float(g_nadjh[ro + tid + 128]) + __bfloat162float(g_nadjl[ro + tid + 128]);
    }
    out_ne[(size_t)g * 256 + tid] = s0 * inv;
    out_ne[(size_t)g * 256 + 128 + tid] = s1 * inv;
}

// ---------------- per-node scalars (neighbors) --------------------------------
__global__ void node_scalars_n(const float* __restrict__ a_src1,
                               const float* __restrict__ a_feat, int T) {
    int row = blockIdx.x * 4 + (threadIdx.x >> 5);
    if (row >= T) return;
    int lane = threadIdx.x & 31;
    const float* h = g_hn + (size_t)row * 128;
    float v[4];
#pragma unroll
    for (int i = 0; i < 4; i++) v[i] = h[lane + 32 * i];
#pragma unroll
    for (int i = 0; i < 4; i++) {
        float s = warpsum(v[i] * a_src1[i * 32 + lane]);
        if (!lane) g_s1n[(size_t)row * 4 + i] = s;
    }
    float fs = 0.f, fd = 0.f;
#pragma unroll
    for (int i = 0; i < 4; i++) {
        fs += v[i] * a_feat[i * 32 + lane];
        fd += v[i] * a_feat[128 + i * 32 + lane];
    }
    fs = warpsum(fs); fd = warpsum(fd);
    if (!lane) { g_fsn[row] = fs; g_fdn[row] = fd; }
}

// ---------------- per-node scalars (centers) ----------------------------------
__global__ void node_scalars_c(const float* __restrict__ a_dst1,
                               const float* __restrict__ a_feat) {
    int row = blockIdx.x * 4 + (threadIdx.x >> 5);
    if (row >= BB) return;
    int lane = threadIdx.x & 31;
    const float* h = g_hc + (size_t)row * 128;
    float v[4];
#pragma unroll
    for (int i = 0; i < 4; i++) v[i] = h[lane + 32 * i];
#pragma unroll
    for (int i = 0; i < 4; i++) {
        float d = warpsum(v[i] * a_dst1[i * 32 + lane]);
        if (!lane) g_d1c[row * 4 + i] = d;
    }
    float fs = 0.f, fd = 0.f;
#pragma unroll
    for (int i = 0; i < 4; i++) {
        fs += v[i] * a_feat[i * 32 + lane];
        fd += v[i] * a_feat[128 + i * 32 + lane];
    }
    fs = warpsum(fs); fd = warpsum(fd);
    if (!lane) { g_fsc[row] = fs; g_fdc[row] = fd; }
}

// ---------------- GAT1 ---------------------------------------------------------
__global__ void __launch_bounds__(128) gat1(
    const float* __restrict__ counts_f, const int* __restrict__ offs,
    const int* __restrict__ edges, int T, float* __restrict__ out_ew) {
    int g = blockIdx.x;
    int tid = threadIdx.x, lane = tid & 31, warp = tid >> 5;
    int base = offs[g];
    int cnt = (int)(counts_f[g] + 0.5f);
    int E2 = 2 * T;
    __shared__ float s_alpha[32][4];
    int head = warp;
    float d1 = g_d1c[g * 4 + head];
    float m = -1e30f;
    for (int t = lane; t < cnt; t += 32) {
        float e = lrelu02(g_s1n[(size_t)(base + t) * 4 + head] + d1);
        s_alpha[t][head] = e;
        m = fmaxf(m, e);
    }
    m = warpmax(m);
    float ssum = 0.f;
    for (int t = lane; t < cnt; t += 32) {
        float ex = expf(s_alpha[t][head] - m);
        s_alpha[t][head] = ex;
        ssum += ex;
    }
    ssum = warpsum(ssum);
    float inv = 1.f / (ssum + 1e-16f);
    for (int t = lane; t < cnt; t += 32) s_alpha[t][head] *= inv;
    __syncthreads();
    int h4 = tid >> 5;
    float acc = 0.f;
    for (int t = 0; t < cnt; t++)
        acc += s_alpha[t][h4] * g_hn[(size_t)(base + t) * 128 + tid];
    size_t xo = (size_t)g * 128 + tid;
    g_xc[xo] = acc;
    __nv_bfloat16 xh = __float2bfloat16(acc);
    g_xch[xo] = xh;
    g_xcl[xo] = __float2bfloat16(acc - __bfloat162float(xh));
    if (tid < cnt) {
        int t = tid;
        int ei = base + t;
        float am = 0.25f * (s_alpha[t][0] + s_alpha[t][1] + s_alpha[t][2] + s_alpha[t][3]);
        float a2 = sigm(g_fsn[ei] + g_fdc[g]);
        float4 r1 = make_float4((float)edges[ei], (float)edges[E2 + ei], am, a2);
        *(float4*)(out_ew + (size_t)ei * 4) = r1;
        int ej = T + ei;
        float a2b = sigm(g_fsc[g] + g_fdn[ei]);
        float4 r2 = make_float4((float)edges[ej], (float)edges[E2 + ej], 1.0f, a2b);
        *(float4*)(out_ew + (size_t)ej * 4) = r2;
    }
}

// ---------------- h2 scalars ----------------------------------------------------
__global__ void h2_scalars(const float* __restrict__ a_src2,
                           const float* __restrict__ a_dst2) {
    int row = blockIdx.x * 4 + (threadIdx.x >> 5);
    if (row >= BB) return;
    int lane = threadIdx.x & 31;
    const float* h = g_h2 + (size_t)row * 128;
    float s = 0.f, d = 0.f;
#pragma unroll
    for (int i = 0; i < 4; i++) {
        float v = h[lane + 32 * i];
        s += v * a_src2[lane + 32 * i];
        d += v * a_dst2[lane + 32 * i];
    }
    s = warpsum(s); d = warpsum(d);
    if (!lane) { g_s2[row] = s; g_d2[row] = d; }
}

// ---------------- VT graph softmax ----------------------------------------------
__global__ void vt_pass1(const int* __restrict__ evt) {
    int i = blockIdx.x * blockDim.x + threadIdx.x;
    if (i >= EVT) return;
    int sv = evt[i], dv = evt[EVT + i];
    float e = lrelu02(g_s2[sv] + g_d2[dv]);
    g_e2v[i] = e;
    atomicMaxFloat(&g_vmax[dv], e);
}
__global__ void vt_pass2(const int* __restrict__ evt) {
    int i = blockIdx.x * blockDim.x + threadIdx.x;
    if (i >= EVT) return;
    int dv = evt[EVT + i];
    float ex = expf(g_e2v[i] - g_vmax[dv]);
    g_e2v[i] = ex;
    atomicAdd(&g_vsum[dv], ex);
}
__global__ void __launch_bounds__(128) vt_pass3(const int* __restrict__ evt,
                                                float* __restrict__ out_alpha,
                                                float* __restrict__ out_xn) {
    int i = blockIdx.x;
    int sv = evt[i], dv = evt[EVT + i];
    float alpha = g_e2v[i] / (g_vsum[dv] + 1e-16f);
    if (threadIdx.x == 0) out_alpha[i] = alpha;
    atomicAdd(&out_xn[(size_t)dv * 128 + threadIdx.x],
              alpha * g_h2[(size_t)sv * 128 + threadIdx.x]);
}

// ---------------- host launcher --------------------------------------------------
extern "C" void kernel_launch(void* const* d_in, const int* in_sizes, int n_in,
                              void* d_out, int out_size) {
    const float* c_in    = (const float*)d_in[0];
    const float* nb_in   = (const float*)d_in[1];
    const float* counts  = (const float*)d_in[2];
    const float* Wq_c    = (const float*)d_in[3];
    const float* Wk_c    = (const float*)d_in[4];
    const float* Wq_n    = (const float*)d_in[5];
    const float* Wk_n    = (const float*)d_in[6];
    const float* W1      = (const float*)d_in[7];
    const float* a_src1  = (const float*)d_in[8];
    const float* a_dst1  = (const float*)d_in[9];
    const float* a_feat  = (const float*)d_in[10];
    const float* W2      = (const float*)d_in[11];
    const float* a_src2  = (const float*)d_in[12];
    const float* a_dst2  = (const float*)d_in[13];
    const int*   seg     = (const int*)d_in[14];
    const int*   offs    = (const int*)d_in[17];
    const int*   edges   = (const int*)d_in[18];
    const int*   evt     = (const int*)d_in[19];
    int T = in_sizes[1] / GG;

    float* out = (float*)d_out;
    float* out_xn   = out;
    float* out_gate = out_xn + (size_t)BB * EMBD;
    float* out_attn = out_gate + (size_t)BB * GG;
    float* out_ne   = out_attn + (size_t)BB * GG;
    float* out_nein = out_ne + (size_t)BB * GG;
    float* out_ew   = out_nein + (size_t)BB * GG;
    float* out_avt  = out_ew + (size_t)8 * T;

    float *p_w, *p_ck, *p_hn, *p_hc, *p_h2;
    cudaGetSymbolAddress((void**)&p_w, g_w);
    cudaGetSymbolAddress((void**)&p_ck, g_ck);
    cudaGetSymbolAddress((void**)&p_hn, g_hn);
    cudaGetSymbolAddress((void**)&p_hc, g_hc);
    cudaGetSymbolAddress((void**)&p_h2, g_h2);

    int tilesT = (T + 127) / 128;

    init_kernel<<<(BB * EMBD + 255) / 256, 256>>>(out_xn);
    compute_M1<<<GG, 256>>>(Wq_c, Wk_c);
    prep_misc<<<704 + BB * 64 / 256, 256>>>(Wq_n, W1, W2, Wk_n, (const float4*)c_in);

    // w = c @ M1  AND  ck = c @ Wk_n via HMMA
    hmma_wck<<<dim3(2, BB / 128, 2), 128>>>(p_w, p_ck);

    stageA<<<BB, 128>>>(c_in, nb_in, counts, offs, out_gate, out_nein);

    // n_adj (bf16 splits) via HMMA + fused tanh gate epilogue
    hmma_gate<<<dim3(2, tilesT), 128>>>(nb_in, p_ck, seg, offs, out_attn, T);
    segmean_nadj<<<BB, 128>>>(counts, offs, out_ne);

    // h = [nadj; cadj] @ W1 via HMMA
    hmma_w1<<<dim3(1, tilesT + BB / 128), 128>>>(p_hn, p_hc, T, BB, tilesT);

    node_scalars_n<<<(T + 3) / 4, 128>>>(a_src1, a_feat, T);
    node_scalars_c<<<BB / 4, 128>>>(a_dst1, a_feat);

    gat1<<<BB, 128>>>(counts, offs, edges, T, out_ew);

    // h2 = xc @ W2 via HMMA
    hmma_h2<<<dim3(1, BB / 128), 128>>>(p_h2);
    h2_scalars<<<BB / 4, 128>>>(a_src2, a_dst2);

    vt_pass1<<<(EVT + 255) / 256, 256>>>(evt);
    vt_pass2<<<(EVT + 255) / 256, 256>>>(evt);
    vt_pass3<<<EVT, 128>>>(evt, out_avt, out_xn);
}

// round 8
// speedup vs baseline: 1.8344x; 1.1684x over previous
#include <cuda_runtime.h>
#include <cuda_bf16.h>
#include <math.h>
#include <stdint.h>

#define BB 8192
#define GG 256
#define EMBD 128
#define NHEAD 4
#define EVT 65536
#define TMAXN 196608  /* 8192 * 24 (counts in [8,24]) */

// ---------------- scratch (static device globals) ----------------------------
__device__ float g_w[BB * GG];
__device__ float g_ck[BB * GG];
__device__ float g_hn[(size_t)TMAXN * EMBD];
__device__ float g_hc[BB * EMBD];
__device__ float g_xc[BB * EMBD];
__device__ float g_h2[BB * EMBD];
__device__ float g_s1n[(size_t)TMAXN * NHEAD];
__device__ float g_d1c[BB * NHEAD];
__device__ float g_fsn[TMAXN];
__device__ float g_fdn[TMAXN];
__device__ float g_fsc[BB];
__device__ float g_fdc[BB];
__device__ float g_s2[BB];
__device__ float g_d2[BB];
__device__ float g_e2v[EVT];
__device__ float g_vmax[BB];
__device__ float g_vsum[BB];
// bf16 split operands
__device__ __nv_bfloat16 g_nh[(size_t)TMAXN * GG];
__device__ __nv_bfloat16 g_nl[(size_t)TMAXN * GG];
__device__ __nv_bfloat16 g_nadjh[(size_t)TMAXN * GG];
__device__ __nv_bfloat16 g_nadjl[(size_t)TMAXN * GG];
__device__ __nv_bfloat16 g_cadjh[BB * GG];
__device__ __nv_bfloat16 g_cadjl[BB * GG];
__device__ __nv_bfloat16 g_ch[BB * GG];
__device__ __nv_bfloat16 g_cl[BB * GG];
__device__ __nv_bfloat16 g_xch[BB * EMBD];
__device__ __nv_bfloat16 g_xcl[BB * EMBD];
__device__ __nv_bfloat16 g_Bqh[GG * GG];    // Wq_n^T  [n][k]
__device__ __nv_bfloat16 g_Bql[GG * GG];
__device__ __nv_bfloat16 g_B1h[EMBD * GG];  // W1^T    [n][k]
__device__ __nv_bfloat16 g_B1l[EMBD * GG];
__device__ __nv_bfloat16 g_BM1h[GG * GG];   // M1^T    [n][k]
__device__ __nv_bfloat16 g_BM1l[GG * GG];
__device__ __nv_bfloat16 g_BWkh[GG * GG];   // Wk_n^T  [n][k]
__device__ __nv_bfloat16 g_BWkl[GG * GG];
__device__ __nv_bfloat16 g_B2h[EMBD * EMBD];// W2^T    [n][k]
__device__ __nv_bfloat16 g_B2l[EMBD * EMBD];

// ---------------- helpers ----------------------------------------------------
__device__ __forceinline__ float warpsum(float v) {
#pragma unroll
    for (int o = 16; o; o >>= 1) v += __shfl_xor_sync(0xffffffffu, v, o);
    return v;
}
__device__ __forceinline__ float warpmax(float v) {
#pragma unroll
    for (int o = 16; o; o >>= 1) v = fmaxf(v, __shfl_xor_sync(0xffffffffu, v, o));
    return v;
}
__device__ __forceinline__ void atomicMaxFloat(float* addr, float value) {
    if (value >= 0.f) atomicMax((int*)addr, __float_as_int(value));
    else              atomicMin((unsigned int*)addr, __float_as_uint(value));
}
__device__ __forceinline__ float lrelu02(float x) { return x > 0.f ? x : 0.2f * x; }
__device__ __forceinline__ float sigm(float x) { return 1.f / (1.f + expf(-x)); }

__device__ __forceinline__ uint32_t smem_u32(const void* p) {
    uint32_t a;
    asm("{ .reg .u64 t; cvta.to.shared.u64 t, %1; cvt.u32.u64 %0, t; }"
        : "=r"(a) : "l"(p));
    return a;
}
__device__ __forceinline__ void bsplit2(float x, float y, uint32_t& h, uint32_t& l) {
    unsigned short hx = __bfloat16_as_ushort(__float2bfloat16(x));
    unsigned short hy = __bfloat16_as_ushort(__float2bfloat16(y));
    float rx = x - __bfloat162float(__ushort_as_bfloat16(hx));
    float ry = y - __bfloat162float(__ushort_as_bfloat16(hy));
    unsigned short lx = __bfloat16_as_ushort(__float2bfloat16(rx));
    unsigned short ly = __bfloat16_as_ushort(__float2bfloat16(ry));
    h = (uint32_t)hx | ((uint32_t)hy << 16);
    l = (uint32_t)lx | ((uint32_t)ly << 16);
}

// ---------------- HMMA primitives --------------------------------------------
__device__ __forceinline__ void ldsm_x4(uint32_t addr, uint32_t& r0, uint32_t& r1,
                                        uint32_t& r2, uint32_t& r3) {
    asm volatile("ldmatrix.sync.aligned.m8n8.x4.shared.b16 {%0,%1,%2,%3}, [%4];"
                 : "=r"(r0), "=r"(r1), "=r"(r2), "=r"(r3) : "r"(addr));
}
__device__ __forceinline__ void mma_bf16(float* c, const uint32_t* a,
                                         uint32_t b0, uint32_t b1) {
    asm volatile(
        "mma.sync.aligned.m16n8k16.row.col.f32.bf16.bf16.f32 "
        "{%0,%1,%2,%3}, {%4,%5,%6,%7}, {%8,%9}, {%0,%1,%2,%3};"
        : "+f"(c[0]), "+f"(c[1]), "+f"(c[2]), "+f"(c[3])
        : "r"(a[0]), "r"(a[1]), "r"(a[2]), "r"(a[3]), "r"(b0), "r"(b1));
}

// cp.async stage: 256 threads, 1 int4/thread, 128 rows x 16 bf16, 48B stride.
__device__ __forceinline__ void stage_async(const __nv_bfloat16* __restrict__ src,
                                            int row0, int M, int k0, int rowElems,
                                            __nv_bfloat16* dst, int tid) {
    int row = tid >> 1, half = tid & 1;
    const void* s = (const uint8_t*)src + (size_t)(row0 + row) * (rowElems * 2) +
                    (size_t)(k0 * 2 + half * 16);
    uint32_t d = smem_u32((uint8_t*)dst + row * 48 + half * 16);
    int sz = (row0 + row < M) ? 16 : 0;
    asm volatile("cp.async.cg.shared.global [%0], [%1], 16, %2;"
                 :: "r"(d), "l"(s), "r"(sz));
}
#define CP_COMMIT() asm volatile("cp.async.commit_group;" ::: "memory")
#define CP_WAIT0()  asm volatile("cp.async.wait_group 0;" ::: "memory")

// 256-thread mainloop: 8 warps (2 row x 4 col), warp tile 64x32.
// Per k-step: stage Ah,Al,Bh,Bl via cp.async; 3 split-products from registers.
#define HMMA_MAINLOOP3(AH_, AL_, BH_, BL_, M_, row0_, col0_, KELA_, KELB_, KSTEPS_) \
    {                                                                          \
        const int lane_ = tid & 31, w_ = tid >> 5;                             \
        const int wr_ = w_ >> 2, wc_ = w_ & 3;                                 \
        const uint32_t aoff_ =                                                 \
            (uint32_t)((wr_ * 64 + (lane_ & 15)) * 48 + (lane_ >> 4) * 16);    \
        const uint32_t boff_ =                                                 \
            (uint32_t)((wc_ * 32 + (lane_ & 15)) * 48 + (lane_ >> 4) * 16);    \
        int buf = 0;                                                           \
        stage_async(AH_, row0_, M_, 0, KELA_, &sA[0][0][0], tid);              \
        stage_async(AL_, row0_, M_, 0, KELA_, &sA[0][1][0], tid);              \
        stage_async(BH_, col0_, 1 << 30, 0, KELB_, &sB[0][0][0], tid);         \
        stage_async(BL_, col0_, 1 << 30, 0, KELB_, &sB[0][1][0], tid);         \
        CP_COMMIT(); CP_WAIT0();                                               \
        __syncthreads();                                                       \
        for (int it = 0; it < (KSTEPS_); it++) {                               \
            if (it + 1 < (KSTEPS_)) {                                          \
                int k0 = (it + 1) * 16;                                        \
                stage_async(AH_, row0_, M_, k0, KELA_, &sA[buf ^ 1][0][0], tid); \
                stage_async(AL_, row0_, M_, k0, KELA_, &sA[buf ^ 1][1][0], tid); \
                stage_async(BH_, col0_, 1 << 30, k0, KELB_, &sB[buf ^ 1][0][0], tid); \
                stage_async(BL_, col0_, 1 << 30, k0, KELB_, &sB[buf ^ 1][1][0], tid); \
                CP_COMMIT();                                                   \
            }                                                                  \
            uint32_t aB0 = smem_u32(&sA[buf][0][0]) + aoff_;                   \
            uint32_t aB1 = smem_u32(&sA[buf][1][0]) + aoff_;                   \
            uint32_t bB0 = smem_u32(&sB[buf][0][0]) + boff_;                   \
            uint32_t bB1 = smem_u32(&sB[buf][1][0]) + boff_;                   \
            uint32_t aH[4][4], aL[4][4], bH[2][4], bL[2][4];                   \
            _Pragma("unroll")                                                  \
            for (int rt = 0; rt < 4; rt++) {                                   \
                ldsm_x4(aB0 + rt * 768, aH[rt][0], aH[rt][1], aH[rt][2], aH[rt][3]); \
                ldsm_x4(aB1 + rt * 768, aL[rt][0], aL[rt][1], aL[rt][2], aL[rt][3]); \
            }                                                                  \
            _Pragma("unroll")                                                  \
            for (int cp = 0; cp < 2; cp++) {                                   \
                ldsm_x4(bB0 + cp * 768, bH[cp][0], bH[cp][1], bH[cp][2], bH[cp][3]); \
                ldsm_x4(bB1 + cp * 768, bL[cp][0], bL[cp][1], bL[cp][2], bL[cp][3]); \
            }                                                                  \
            _Pragma("unroll")                                                  \
            for (int rt = 0; rt < 4; rt++)                                     \
                _Pragma("unroll")                                              \
                for (int cp = 0; cp < 2; cp++) {                               \
                    mma_bf16(acc[rt][2 * cp],     aH[rt], bH[cp][0], bH[cp][2]); \
                    mma_bf16(acc[rt][2 * cp + 1], aH[rt], bH[cp][1], bH[cp][3]); \
                    mma_bf16(acc[rt][2 * cp],     aH[rt], bL[cp][0], bL[cp][2]); \
                    mma_bf16(acc[rt][2 * cp + 1], aH[rt], bL[cp][1], bL[cp][3]); \
                    mma_bf16(acc[rt][2 * cp],     aL[rt], bH[cp][0], bH[cp][2]); \
                    mma_bf16(acc[rt][2 * cp + 1], aL[rt], bH[cp][1], bH[cp][3]); \
                }                                                              \
            if (it + 1 < (KSTEPS_)) CP_WAIT0();                                \
            __syncthreads();                                                   \
            buf ^= 1;                                                          \
        }                                                                      \
    }

#define SMEM_DECL                                                              \
    __shared__ __align__(16) __nv_bfloat16 sA[2][2][128 * 24];                 \
    __shared__ __align__(16) __nv_bfloat16 sB[2][2][128 * 24];

// Epilogue index helpers (256 threads): warp tile 64x32.
#define EPI_VARS                                                               \
    const int lane = tid & 31, w = tid >> 5, wr = w >> 2, wc = w & 3;          \
    const int g = lane >> 2, q = lane & 3;

// ---------------- merged prep kernel ------------------------------------------
__global__ void prep_misc(const float* __restrict__ Wq_n,
                          const float* __restrict__ W1,
                          const float* __restrict__ W2,
                          const float* __restrict__ Wk_n,
                          const float4* __restrict__ cin) {
    int b = blockIdx.x, tid = threadIdx.x;
    if (b < 256) {
        int idx = b * 256 + tid, k = idx >> 8, n = idx & 255;
        float x = Wq_n[k * 256 + n];
        __nv_bfloat16 h = __float2bfloat16(x);
        g_Bqh[n * 256 + k] = h;
        g_Bql[n * 256 + k] = __float2bfloat16(x - __bfloat162float(h));
    } else if (b < 384) {
        int idx = (b - 256) * 256 + tid, k = idx >> 7, n = idx & 127;
        float x = W1[k * 128 + n];
        __nv_bfloat16 h = __float2bfloat16(x);
        g_B1h[n * 256 + k] = h;
        g_B1l[n * 256 + k] = __float2bfloat16(x - __bfloat162float(h));
    } else if (b < 448) {
        int idx = (b - 384) * 256 + tid, k = idx >> 7, n = idx & 127;
        float x = W2[k * 128 + n];
        __nv_bfloat16 h = __float2bfloat16(x);
        g_B2h[n * 128 + k] = h;
        g_B2l[n * 128 + k] = __float2bfloat16(x - __bfloat162float(h));
    } else if (b < 704) {
        int idx = (b - 448) * 256 + tid, k = idx >> 8, n = idx & 255;
        float x = Wk_n[k * 256 + n];
        __nv_bfloat16 h = __float2bfloat16(x);
        g_BWkh[n * 256 + k] = h;
        g_BWkl[n * 256 + k] = __float2bfloat16(x - __bfloat162float(h));
    } else {
        int i = (b - 704) * 256 + tid;
        float4 v = cin[i];
        uint32_t h0, l0, h1, l1;
        bsplit2(v.x, v.y, h0, l0);
        bsplit2(v.z, v.w, h1, l1);
        ((uint32_t*)g_ch)[i * 2] = h0; ((uint32_t*)g_ch)[i * 2 + 1] = h1;
        ((uint32_t*)g_cl)[i * 2] = l0; ((uint32_t*)g_cl)[i * 2 + 1] = l1;
    }
}

// ---------------- M1 = Wq_c @ Wk_c^T, fused transposed split ------------------
__global__ void compute_M1(const float* __restrict__ Wq_c,
                           const float* __restrict__ Wk_c) {
    int p = blockIdx.x;
    int tid = threadIdx.x, lane = tid & 31, warp = tid >> 5;
    __shared__ float sq[128];
    if (tid < 128) sq[tid] = Wq_c[p * 128 + tid];
    __syncthreads();
    for (int k = warp; k < 256; k += 8) {
        const float* row = Wk_c + (size_t)k * 128;
        float acc = 0.f;
#pragma unroll
        for (int i = 0; i < 4; i++) acc += row[lane + 32 * i] * sq[lane + 32 * i];
        acc = warpsum(acc);
        if (!lane) {
            __nv_bfloat16 h = __float2bfloat16(acc);
            g_BM1h[k * 256 + p] = h;
            g_BM1l[k * 256 + p] = __float2bfloat16(acc - __bfloat162float(h));
        }
    }
}

// ================= HMMA GEMM: w/ck dual-B =====================================
__global__ void __launch_bounds__(256) hmma_wck(float* __restrict__ Cw,
                                                float* __restrict__ Cck) {
    SMEM_DECL
    const int tid = threadIdx.x;
    const int row0 = blockIdx.y * 128, col0 = blockIdx.x * 128;
    const __nv_bfloat16* Bh = blockIdx.z ? g_BWkh : g_BM1h;
    const __nv_bfloat16* Bl = blockIdx.z ? g_BWkl : g_BM1l;
    float* C = blockIdx.z ? Cck : Cw;
    float acc[4][4][4] = {};
    HMMA_MAINLOOP3(g_ch, g_cl, Bh, Bl, BB, row0, col0, 256, 256, 16);
    EPI_VARS
#pragma unroll
    for (int rt = 0; rt < 4; rt++)
#pragma unroll
        for (int i = 0; i < 2; i++) {
            int er = row0 + wr * 64 + rt * 16 + g + i * 8;
            float* crow = C + (size_t)er * 256;
#pragma unroll
            for (int ct = 0; ct < 4; ct++) {
                int c = col0 + wc * 32 + ct * 8 + q * 2;
                *(float2*)(crow + c) = make_float2(acc[rt][ct][i * 2 + 0],
                                                   acc[rt][ct][i * 2 + 1]);
            }
        }
}

// ================= HMMA GEMM: gate ============================================
__global__ void __launch_bounds__(256) hmma_gate(
    const float* __restrict__ Afp, const float* __restrict__ ck,
    const int* __restrict__ seg, const int* __restrict__ offs,
    float* __restrict__ out_attn, int M) {
    SMEM_DECL
    const int tid = threadIdx.x;
    const int row0 = blockIdx.y * 128, col0 = blockIdx.x * 128;
    float acc[4][4][4] = {};
    HMMA_MAINLOOP3(g_nh, g_nl, g_Bqh, g_Bql, M, row0, col0, 256, 256, 16);
    EPI_VARS
#pragma unroll
    for (int rt = 0; rt < 4; rt++)
#pragma unroll
        for (int i = 0; i < 2; i++) {
            int er = row0 + wr * 64 + rt * 16 + g + i * 8;
            if (er >= M) continue;
            int sg = seg[er];
            bool first = (offs[sg] == er);
            const float* ckrow = ck + (size_t)sg * 256;
            const float* arow = Afp + (size_t)er * 256;
#pragma unroll
            for (int ct = 0; ct < 4; ct++) {
                int c = col0 + wc * 32 + ct * 8 + q * 2;
                float2 ckv = *(const float2*)(ckrow + c);
                float2 av = *(const float2*)(arow + c);
                float g0 = tanhf(acc[rt][ct][i * 2 + 0] * ckv.x);
                float g1 = tanhf(acc[rt][ct][i * 2 + 1] * ckv.y);
                uint32_t hh, ll;
                bsplit2(av.x * g0, av.y * g1, hh, ll);
                *(uint32_t*)((uint8_t*)g_nadjh + (size_t)er * 512 + c * 2) = hh;
                *(uint32_t*)((uint8_t*)g_nadjl + (size_t)er * 512 + c * 2) = ll;
                if (first)
                    *(float2*)(out_attn + (size_t)sg * 256 + c) = make_float2(g0, g1);
            }
        }
}

// ================= HMMA GEMM: [nadj; cadj] @ W1 ===============================
__global__ void __launch_bounds__(256) hmma_w1(
    float* __restrict__ C0, float* __restrict__ C1,
    int M0, int M1, int tiles0) {
    SMEM_DECL
    const int tid = threadIdx.x;
    int t = blockIdx.y;
    const __nv_bfloat16 *Ah, *Al;
    float* C; int M, row0;
    if (t < tiles0) { Ah = g_nadjh; Al = g_nadjl; C = C0; M = M0; row0 = t * 128; }
    else            { Ah = g_cadjh; Al = g_cadjl; C = C1; M = M1; row0 = (t - tiles0) * 128; }
    float acc[4][4][4] = {};
    HMMA_MAINLOOP3(Ah, Al, g_B1h, g_B1l, M, row0, 0, 256, 256, 16);
    EPI_VARS
#pragma unroll
    for (int rt = 0; rt < 4; rt++)
#pragma unroll
        for (int i = 0; i < 2; i++) {
            int er = row0 + wr * 64 + rt * 16 + g + i * 8;
            if (er >= M) continue;
            float* crow = C + (size_t)er * 128;
#pragma unroll
            for (int ct = 0; ct < 4; ct++) {
                int c = wc * 32 + ct * 8 + q * 2;
                *(float2*)(crow + c) = make_float2(acc[rt][ct][i * 2 + 0],
                                                   acc[rt][ct][i * 2 + 1]);
            }
        }
}

// ================= HMMA GEMM: h2 = xc @ W2  (K=128, N=128) ====================
__global__ void __launch_bounds__(256) hmma_h2(float* __restrict__ C) {
    SMEM_DECL
    const int tid = threadIdx.x;
    const int row0 = blockIdx.y * 128;
    float acc[4][4][4] = {};
    HMMA_MAINLOOP3(g_xch, g_xcl, g_B2h, g_B2l, BB, row0, 0, 128, 128, 8);
    EPI_VARS
#pragma unroll
    for (int rt = 0; rt < 4; rt++)
#pragma unroll
        for (int i = 0; i < 2; i++) {
            int er = row0 + wr * 64 + rt * 16 + g + i * 8;
            float* crow = C + (size_t)er * 128;
#pragma unroll
            for (int ct = 0; ct < 4; ct++) {
                int c = wc * 32 + ct * 8 + q * 2;
                *(float2*)(crow + c) = make_float2(acc[rt][ct][i * 2 + 0],
                                                   acc[rt][ct][i * 2 + 1]);
            }
        }
}

// ---------------- init --------------------------------------------------------
__global__ void init_kernel(float* __restrict__ out_xn) {
    int i = blockIdx.x * blockDim.x + threadIdx.x;
    if (i < BB * EMBD) out_xn[i] = 0.f;
    if (i < BB) { g_vmax[i] = -1e30f; g_vsum[i] = 0.f; }
}

// ---------------- stage A: cross-attention + n/cadj splits --------------------
__global__ void __launch_bounds__(128) stageA(
    const float* __restrict__ cin, const float* __restrict__ nin,
    const float* __restrict__ counts_f, const int* __restrict__ offs,
    float* __restrict__ out_gate, float* __restrict__ out_nein) {
    int g = blockIdx.x;
    int tid = threadIdx.x, lane = tid & 31, warp = tid >> 5;
    int base = offs[g];
    int cnt = (int)(counts_f[g] + 0.5f);
    __shared__ float s_w[256];
    __shared__ float s_attn[32];
    s_w[tid] = g_w[(size_t)g * 256 + tid];
    s_w[tid + 128] = g_w[(size_t)g * 256 + 128 + tid];
    __syncthreads();
    for (int t = warp; t < cnt; t += 4) {
        const float* row = nin + (size_t)(base + t) * 256;
        float acc = 0.f;
#pragma unroll
        for (int i = 0; i < 8; i++) acc += row[lane + 32 * i] * s_w[lane + 32 * i];
        acc = warpsum(acc);
        if (!lane) s_attn[t] = acc * 0.08838834764831845f;
    }
    __syncthreads();
    if (tid == 0) {
        float m = -1e30f;
        for (int t = 0; t < cnt; t++) m = fmaxf(m, s_attn[t]);
        float s = 0.f;
        for (int t = 0; t < cnt; t++) { float e = expf(s_attn[t] - m); s_attn[t] = e; s += e; }
        float inv = 1.f / (s + 1e-16f);
        for (int t = 0; t < cnt; t++) s_attn[t] *= inv;
    }
    __syncthreads();
    float acc0 = 0.f, acc1 = 0.f, sum0 = 0.f, sum1 = 0.f;
    for (int t = 0; t < cnt; t++) {
        size_t ro = (size_t)(base + t) * 256;
        const float* row = nin + ro;
        float v0 = row[tid], v1 = row[tid + 128];
        float a = s_attn[t];
        acc0 += a * v0; acc1 += a * v1;
        sum0 += v0;     sum1 += v1;
        __nv_bfloat16 nh0 = __float2bfloat16(v0);
        __nv_bfloat16 nh1 = __float2bfloat16(v1);
        g_nh[ro + tid] = nh0;           g_nh[ro + tid + 128] = nh1;
        g_nl[ro + tid] = __float2bfloat16(v0 - __bfloat162float(nh0));
        g_nl[ro + tid + 128] = __float2bfloat16(v1 - __bfloat162float(nh1));
    }
    float gate0 = tanhf(acc0), gate1 = tanhf(acc1);
    size_t o = (size_t)g * 256 + tid;
    float c0 = cin[o], c1 = cin[o + 128];
    out_gate[o] = gate0;            out_gate[o + 128] = gate1;
    float ca0 = c0 * gate0, ca1 = c1 * gate1;
    __nv_bfloat16 h0 = __float2bfloat16(ca0);
    __nv_bfloat16 h1 = __float2bfloat16(ca1);
    g_cadjh[o] = h0;                g_cadjh[o + 128] = h1;
    g_cadjl[o] = __float2bfloat16(ca0 - __bfloat162float(h0));
    g_cadjl[o + 128] = __float2bfloat16(ca1 - __bfloat162float(h1));
    out_nein[o] = c0 + sum0;        out_nein[o + 128] = c1 + sum1;
}

// ---------------- neighb_expr from bf16 splits --------------------------------
__global__ void __launch_bounds__(128) segmean_nadj(
    const float* __restrict__ counts_f, const int* __restrict__ offs,
    float* __restrict__ out_ne) {
    int g = blockIdx.x;
    int tid = threadIdx.x;
    int base = offs[g];
    int cnt = (int)(counts_f[g] + 0.5f);
    float inv = 1.f / counts_f[g];
    float s0 = 0.f, s1 = 0.f;
    for (int t = 0; t < cnt; t++) {
        size_t ro = (size_t)(base + t) * 256;
        s0 += __bfloat162float(g_nadjh[ro + tid]) + __bfloat162float(g_nadjl[ro + tid]);
        s1 += __bfloat162float(g_nadjh[ro + tid + 128]) + __bfloat162float(g_nadjl[ro + tid + 128]);
    }
    out_ne[(size_t)g * 256 + tid] = s0 * inv;
    out_ne[(size_t)g * 256 + 128 + tid] = s1 * inv;
}

// ---------------- per-node scalars (neighbors) --------------------------------
__global__ void node_scalars_n(const float* __restrict__ a_src1,
                               const float* __restrict__ a_feat, int T) {
    int row = blockIdx.x * 4 + (threadIdx.x >> 5);
    if (row >= T) return;
    int lane = threadIdx.x & 31;
    const float* h = g_hn + (size_t)row * 128;
    float v[4];
#pragma unroll
    for (int i = 0; i < 4; i++) v[i] = h[lane + 32 * i];
#pragma unroll
    for (int i = 0; i < 4; i++) {
        float s = warpsum(v[i] * a_src1[i * 32 + lane]);
        if (!lane) g_s1n[(size_t)row * 4 + i] = s;
    }
    float fs = 0.f, fd = 0.f;
#pragma unroll
    for (int i = 0; i < 4; i++) {
        fs += v[i] * a_feat[i * 32 + lane];
        fd += v[i] * a_feat[128 + i * 32 + lane];
    }
    fs = warpsum(fs); fd = warpsum(fd);
    if (!lane) { g_fsn[row] = fs; g_fdn[row] = fd; }
}

// ---------------- per-node scalars (centers) ----------------------------------
__global__ void node_scalars_c(const float* __restrict__ a_dst1,
                               const float* __restrict__ a_feat) {
    int row = blockIdx.x * 4 + (threadIdx.x >> 5);
    if (row >= BB) return;
    int lane = threadIdx.x & 31;
    const float* h = g_hc + (size_t)row * 128;
    float v[4];
#pragma unroll
    for (int i = 0; i < 4; i++) v[i] = h[lane + 32 * i];
#pragma unroll
    for (int i = 0; i < 4; i++) {
        float d = warpsum(v[i] * a_dst1[i * 32 + lane]);
        if (!lane) g_d1c[row * 4 + i] = d;
    }
    float fs = 0.f, fd = 0.f;
#pragma unroll
    for (int i = 0; i < 4; i++) {
        fs += v[i] * a_feat[i * 32 + lane];
        fd += v[i] * a_feat[128 + i * 32 + lane];
    }
    fs = warpsum(fs); fd = warpsum(fd);
    if (!lane) { g_fsc[row] = fs; g_fdc[row] = fd; }
}

// ---------------- GAT1 ---------------------------------------------------------
__global__ void __launch_bounds__(128) gat1(
    const float* __restrict__ counts_f, const int* __restrict__ offs,
    const int* __restrict__ edges, int T, float* __restrict__ out_ew) {
    int g = blockIdx.x;
    int tid = threadIdx.x, lane = tid & 31, warp = tid >> 5;
    int base = offs[g];
    int cnt = (int)(counts_f[g] + 0.5f);
    int E2 = 2 * T;
    __shared__ float s_alpha[32][4];
    int head = warp;
    float d1 = g_d1c[g * 4 + head];
    float m = -1e30f;
    for (int t = lane; t < cnt; t += 32) {
        float e = lrelu02(g_s1n[(size_t)(base + t) * 4 + head] + d1);
        s_alpha[t][head] = e;
        m = fmaxf(m, e);
    }
    m = warpmax(m);
    float ssum = 0.f;
    for (int t = lane; t < cnt; t += 32) {
        float ex = expf(s_alpha[t][head] - m);
        s_alpha[t][head] = ex;
        ssum += ex;
    }
    ssum = warpsum(ssum);
    float inv = 1.f / (ssum + 1e-16f);
    for (int t = lane; t < cnt; t += 32) s_alpha[t][head] *= inv;
    __syncthreads();
    int h4 = tid >> 5;
    float acc = 0.f;
    for (int t = 0; t < cnt; t++)
        acc += s_alpha[t][h4] * g_hn[(size_t)(base + t) * 128 + tid];
    size_t xo = (size_t)g * 128 + tid;
    g_xc[xo] = acc;
    __nv_bfloat16 xh = __float2bfloat16(acc);
    g_xch[xo] = xh;
    g_xcl[xo] = __float2bfloat16(acc - __bfloat162float(xh));
    if (tid < cnt) {
        int t = tid;
        int ei = base + t;
        float am = 0.25f * (s_alpha[t][0] + s_alpha[t][1] + s_alpha[t][2] + s_alpha[t][3]);
        float a2 = sigm(g_fsn[ei] + g_fdc[g]);
        float4 r1 = make_float4((float)edges[ei], (float)edges[E2 + ei], am, a2);
        *(float4*)(out_ew + (size_t)ei * 4) = r1;
        int ej = T + ei;
        float a2b = sigm(g_fsc[g] + g_fdn[ei]);
        float4 r2 = make_float4((float)edges[ej], (float)edges[E2 + ej], 1.0f, a2b);
        *(float4*)(out_ew + (size_t)ej * 4) = r2;
    }
}

// ---------------- h2 scalars ----------------------------------------------------
__global__ void h2_scalars(const float* __restrict__ a_src2,
                           const float* __restrict__ a_dst2) {
    int row = blockIdx.x * 4 + (threadIdx.x >> 5);
    if (row >= BB) return;
    int lane = threadIdx.x & 31;
    const float* h = g_h2 + (size_t)row * 128;
    float s = 0.f, d = 0.f;
#pragma unroll
    for (int i = 0; i < 4; i++) {
        float v = h[lane + 32 * i];
        s += v * a_src2[lane + 32 * i];
        d += v * a_dst2[lane + 32 * i];
    }
    s = warpsum(s); d = warpsum(d);
    if (!lane) { g_s2[row] = s; g_d2[row] = d; }
}

// ---------------- VT graph softmax ----------------------------------------------
__global__ void vt_pass1(const int* __restrict__ evt) {
    int i = blockIdx.x * blockDim.x + threadIdx.x;
    if (i >= EVT) return;
    int sv = evt[i], dv = evt[EVT + i];
    float e = lrelu02(g_s2[sv] + g_d2[dv]);
    g_e2v[i] = e;
    atomicMaxFloat(&g_vmax[dv], e);
}
__global__ void vt_pass2(const int* __restrict__ evt) {
    int i = blockIdx.x * blockDim.x + threadIdx.x;
    if (i >= EVT) return;
    int dv = evt[EVT + i];
    float ex = expf(g_e2v[i] - g_vmax[dv]);
    g_e2v[i] = ex;
    atomicAdd(&g_vsum[dv], ex);
}
__global__ void __launch_bounds__(128) vt_pass3(const int* __restrict__ evt,
                                                float* __restrict__ out_alpha,
                                                float* __restrict__ out_xn) {
    int i = blockIdx.x;
    int sv = evt[i], dv = evt[EVT + i];
    float alpha = g_e2v[i] / (g_vsum[dv] + 1e-16f);
    if (threadIdx.x == 0) out_alpha[i] = alpha;
    atomicAdd(&out_xn[(size_t)dv * 128 + threadIdx.x],
              alpha * g_h2[(size_t)sv * 128 + threadIdx.x]);
}

// ---------------- host launcher --------------------------------------------------
extern "C" void kernel_launch(void* const* d_in, const int* in_sizes, int n_in,
                              void* d_out, int out_size) {
    const float* c_in    = (const float*)d_in[0];
    const float* nb_in   = (const float*)d_in[1];
    const float* counts  = (const float*)d_in[2];
    const float* Wq_c    = (const float*)d_in[3];
    const float* Wk_c    = (const float*)d_in[4];
    const float* Wq_n    = (const float*)d_in[5];
    const float* Wk_n    = (const float*)d_in[6];
    const float* W1      = (const float*)d_in[7];
    const float* a_src1  = (const float*)d_in[8];
    const float* a_dst1  = (const float*)d_in[9];
    const float* a_feat  = (const float*)d_in[10];
    const float* W2      = (const float*)d_in[11];
    const float* a_src2  = (const float*)d_in[12];
    const float* a_dst2  = (const float*)d_in[13];
    const int*   seg     = (const int*)d_in[14];
    const int*   offs    = (const int*)d_in[17];
    const int*   edges   = (const int*)d_in[18];
    const int*   evt     = (const int*)d_in[19];
    int T = in_sizes[1] / GG;

    float* out = (float*)d_out;
    float* out_xn   = out;
    float* out_gate = out_xn + (size_t)BB * EMBD;
    float* out_attn = out_gate + (size_t)BB * GG;
    float* out_ne   = out_attn + (size_t)BB * GG;
    float* out_nein = out_ne + (size_t)BB * GG;
    float* out_ew   = out_nein + (size_t)BB * GG;
    float* out_avt  = out_ew + (size_t)8 * T;

    float *p_w, *p_ck, *p_hn, *p_hc, *p_h2;
    cudaGetSymbolAddress((void**)&p_w, g_w);
    cudaGetSymbolAddress((void**)&p_ck, g_ck);
    cudaGetSymbolAddress((void**)&p_hn, g_hn);
    cudaGetSymbolAddress((void**)&p_hc, g_hc);
    cudaGetSymbolAddress((void**)&p_h2, g_h2);

    int tilesT = (T + 127) / 128;

    init_kernel<<<(BB * EMBD + 255) / 256, 256>>>(out_xn);
    compute_M1<<<GG, 256>>>(Wq_c, Wk_c);
    prep_misc<<<704 + BB * 64 / 256, 256>>>(Wq_n, W1, W2, Wk_n, (const float4*)c_in);

    hmma_wck<<<dim3(2, BB / 128, 2), 256>>>(p_w, p_ck);

    stageA<<<BB, 128>>>(c_in, nb_in, counts, offs, out_gate, out_nein);

    hmma_gate<<<dim3(2, tilesT), 256>>>(nb_in, p_ck, seg, offs, out_attn, T);
    segmean_nadj<<<BB, 128>>>(counts, offs, out_ne);

    hmma_w1<<<dim3(1, tilesT + BB / 128), 256>>>(p_hn, p_hc, T, BB, tilesT);

    node_scalars_n<<<(T + 3) / 4, 128>>>(a_src1, a_feat, T);
    node_scalars_c<<<BB / 4, 128>>>(a_dst1, a_feat);

    gat1<<<BB, 128>>>(counts, offs, edges, T, out_ew);

    hmma_h2<<<dim3(1, BB / 128), 256>>>(p_h2);
    h2_scalars<<<BB / 4, 128>>>(a_src2, a_dst2);

    vt_pass1<<<(EVT + 255) / 256, 256>>>(evt);
    vt_pass2<<<(EVT + 255) / 256, 256>>>(evt);
    vt_pass3<<<EVT, 128>>>(evt, out_avt, out_xn);
}